// round 11
// baseline (speedup 1.0000x reference)
#include <cuda_runtime.h>

#define CELL_N 76
#define DRUG_N 764
#define TOT_N  840
#define BATCH  4096
#define NPROT  15970
#define KSPLIT 4
#define KCHUNK 2048  // 8192 / KSPLIT
#define TSQ_N  ((NPROT + 7) / 8)   // 1997 tablesq blocks

// ---------------- scratch (device globals; no allocs allowed) ----------------
__device__ float g_pool1[TOT_N * 4 * 64 * 64];
__device__ float g_pool2[TOT_N * 8 * 32 * 32];
__device__ float g_fcp  [KSPLIT * TOT_N * 64];
__device__ float g_item [TOT_N * 64];
__device__ float g_stat [4 * 64];          // [mean_c, inv_c, mean_d, inv_d]
__device__ float g_emb  [TOT_N * 64];
__device__ float g_normsq[TOT_N];
__device__ float g_U    [CELL_N * 128];
__device__ float g_tablesq[NPROT];

// ---------------- tablesq (blocks first) + conv1 (merged cell+drug) ----------------
__global__ void __launch_bounds__(256, 6) k_conv1(
        const float* __restrict__ cell_pre, const float* __restrict__ drug_pre,
        const float* __restrict__ w, const float* __restrict__ b,
        const float* __restrict__ table) {
    int blk = blockIdx.x;
    int tid = threadIdx.x;
    if (blk < TSQ_N) {
        int warp = blk * 8 + (tid >> 5);
        int lane = tid & 31;
        if (warp >= NPROT) return;
        const float* r = table + warp * 64;
        float a = r[lane], bb = r[lane + 32];
        float s = a * a + bb * bb;
        #pragma unroll
        for (int o = 16; o; o >>= 1) s += __shfl_down_sync(0xffffffffu, s, o);
        if (lane == 0) g_tablesq[warp] = s;
        return;
    }
    int cblk = blk - TSQ_N;
    int half = cblk & 1;
    int gn;
    const float* x;
    if (cblk < 2 * CELL_N) { gn = cblk >> 1; x = cell_pre + gn * 16384; }
    else { int n = (cblk - 2 * CELL_N) >> 1; gn = CELL_N + n; x = drug_pre + n * 16384; }
    __shared__ float tile[66 * 130];
    __shared__ float ws1[36];
    __shared__ float bs1[4];
    if (tid < 36) ws1[tid] = w[tid];
    if (tid < 4)  bs1[tid] = b[tid];
    int row0 = half * 64 - 1;
    for (int idx = tid; idx < 66 * 130; idx += 256) {
        int r = idx / 130, c = idx - r * 130;
        int y = row0 + r, xx = c - 1;
        tile[idx] = (y >= 0 && y < 128 && (unsigned)xx < 128u) ? x[y * 128 + xx] : 0.f;
    }
    __syncthreads();
    #pragma unroll
    for (int i = 0; i < 8; i++) {
        int pos = tid + i * 256;
        int oy = pos >> 6, ox = pos & 63;
        float p[4][4];
        #pragma unroll
        for (int r = 0; r < 4; r++) {
            const float2* s = (const float2*)&tile[(2 * oy + r) * 130 + 2 * ox];
            float2 a = s[0], d = s[1];
            p[r][0] = a.x; p[r][1] = a.y; p[r][2] = d.x; p[r][3] = d.y;
        }
        #pragma unroll
        for (int oc = 0; oc < 4; oc++) {
            float wr[9];
            #pragma unroll
            for (int t = 0; t < 9; t++) wr[t] = ws1[oc * 9 + t];
            float bv = bs1[oc];
            float q00 = bv, q01 = bv, q10 = bv, q11 = bv;
            #pragma unroll
            for (int dy = 0; dy < 3; dy++)
            #pragma unroll
            for (int dx = 0; dx < 3; dx++) {
                float wv = wr[dy * 3 + dx];
                q00 += p[dy    ][dx    ] * wv;
                q01 += p[dy    ][dx + 1] * wv;
                q10 += p[dy + 1][dx    ] * wv;
                q11 += p[dy + 1][dx + 1] * wv;
            }
            float m = fmaxf(fmaxf(q00, q01), fmaxf(q10, q11));
            g_pool1[((gn * 4 + oc) * 64 + half * 32 + oy) * 64 + ox] = fmaxf(m, 0.f);
        }
    }
}

// ---------------- conv2 (4->8) + relu + pool, weight window -> 5 CTAs/SM ----------------
#define C2_STR 68
#define C2_CH  (34 * C2_STR)
__global__ void __launch_bounds__(256, 5) k_conv2(
        const float* __restrict__ w, const float* __restrict__ b) {
    int n = blockIdx.x >> 1, half = blockIdx.x & 1;
    __shared__ float tile[4 * C2_CH];
    __shared__ float ws[288];
    int tid = threadIdx.x;
    int row0 = half * 32 - 1;
    for (int i = tid; i < 288; i += 256) ws[i] = w[i];
    for (int idx = tid; idx < 4 * 34 * 66; idx += 256) {
        int c = idx / (34 * 66), rem = idx - c * (34 * 66);
        int r = rem / 66, cc = rem - r * 66;
        int y = row0 + r, xx = cc - 1;
        tile[c * C2_CH + r * C2_STR + cc] =
            ((unsigned)y < 64u && (unsigned)xx < 64u)
          ? g_pool1[((n * 4 + c) * 64 + y) * 64 + xx] : 0.f;
    }
    __syncthreads();
    int oc = tid >> 5, lane = tid & 31;
    float bs = b[oc];
    #pragma unroll
    for (int i = 0; i < 8; i++) {
        int pos = lane + i * 32;
        int oy = pos >> 4, oxp = pos & 15;
        float q[8];
        #pragma unroll
        for (int k = 0; k < 8; k++) q[k] = bs;
        #pragma unroll
        for (int c = 0; c < 4; c++) {
            float pt[4][6];
            #pragma unroll
            for (int rr = 0; rr < 4; rr++) {
                const float* base = &tile[c * C2_CH + (2 * oy + rr) * C2_STR + 4 * oxp];
                float4 a = *(const float4*)base;
                float2 b2 = *(const float2*)(base + 4);
                pt[rr][0] = a.x; pt[rr][1] = a.y; pt[rr][2] = a.z;
                pt[rr][3] = a.w; pt[rr][4] = b2.x; pt[rr][5] = b2.y;
            }
            float wr[9];
            #pragma unroll
            for (int t = 0; t < 9; t++) wr[t] = ws[oc * 36 + c * 9 + t];
            #pragma unroll
            for (int dy = 0; dy < 3; dy++)
            #pragma unroll
            for (int dx = 0; dx < 3; dx++) {
                float wv = wr[dy * 3 + dx];
                q[0] += pt[dy    ][dx    ] * wv;
                q[1] += pt[dy    ][dx + 1] * wv;
                q[2] += pt[dy + 1][dx    ] * wv;
                q[3] += pt[dy + 1][dx + 1] * wv;
                q[4] += pt[dy    ][dx + 2] * wv;
                q[5] += pt[dy    ][dx + 3] * wv;
                q[6] += pt[dy + 1][dx + 2] * wv;
                q[7] += pt[dy + 1][dx + 3] * wv;
            }
        }
        float m0 = fmaxf(fmaxf(q[0], q[1]), fmaxf(q[2], q[3]));
        float m1 = fmaxf(fmaxf(q[4], q[5]), fmaxf(q[6], q[7]));
        float2 v = make_float2(fmaxf(m0, 0.f), fmaxf(m1, 0.f));
        *(float2*)&g_pool2[((n * 8 + oc) * 32 + half * 16 + oy) * 32 + 2 * oxp] = v;
    }
}

// ---------------- FC as tiled GEMM with K-split ----------------
__global__ void __launch_bounds__(256) k_fc(const float* __restrict__ W) {
    int m0 = blockIdx.x * 32;
    int kb = blockIdx.y;
    int k0 = kb * KCHUNK;
    __shared__ float Xs[32][64];
    __shared__ float Ws[64][68];
    int tid = threadIdx.x;
    int tm = tid >> 5, tn = tid & 31;
    float acc[4][2] = {};
    for (int kt = 0; kt < KCHUNK; kt += 64) {
        #pragma unroll
        for (int i = 0; i < 8; i++) {
            int idx = tid + i * 256;
            int r = idx >> 6, c = idx & 63;
            int m = m0 + r;
            Xs[r][c] = (m < TOT_N) ? g_pool2[m * 8192 + k0 + kt + c] : 0.f;
        }
        #pragma unroll
        for (int i = 0; i < 16; i++) {
            int idx = tid + i * 256;
            int j = idx >> 6, c = idx & 63;
            Ws[j][c] = W[j * 8192 + k0 + kt + c];
        }
        __syncthreads();
        #pragma unroll
        for (int kk = 0; kk < 64; kk += 4) {
            float4 w0 = *(const float4*)&Ws[tn     ][kk];
            float4 w1 = *(const float4*)&Ws[tn + 32][kk];
            #pragma unroll
            for (int r = 0; r < 4; r++) {
                float4 xv = *(const float4*)&Xs[tm * 4 + r][kk];
                acc[r][0] += xv.x * w0.x + xv.y * w0.y + xv.z * w0.z + xv.w * w0.w;
                acc[r][1] += xv.x * w1.x + xv.y * w1.y + xv.z * w1.z + xv.w * w1.w;
            }
        }
        __syncthreads();
    }
    #pragma unroll
    for (int r = 0; r < 4; r++) {
        int m = m0 + tm * 4 + r;
        if (m < TOT_N) {
            g_fcp[(kb * TOT_N + m) * 64 + tn     ] = acc[r][0];
            g_fcp[(kb * TOT_N + m) * 64 + tn + 32] = acc[r][1];
        }
    }
}

// ---------------- reduce K-split partials + bias -> g_item (float4) ----------------
__global__ void k_fcred(const float* __restrict__ b) {
    int v = blockIdx.x * blockDim.x + threadIdx.x;     // float4 index
    if (v >= TOT_N * 16) return;
    int j4 = (v & 15) * 4;
    float4 s = *(const float4*)&b[j4];
    #pragma unroll
    for (int kb = 0; kb < KSPLIT; kb++) {
        float4 p = *(const float4*)&g_fcp[kb * TOT_N * 64 + v * 4];
        s.x += p.x; s.y += p.y; s.z += p.z; s.w += p.w;
    }
    *(float4*)&g_item[v * 4] = s;
}

// ---------------- stats only: mean + rsqrt(var) per feature per group ----------------
template<int ROW0, int N, int SBASE>
__device__ __forceinline__ void stats_body(float2* red) {
    int tid = threadIdx.x;
    int j = tid & 63, q = tid >> 6;
    constexpr int R = (N + 15) / 16;
    float s = 0.f, ss = 0.f;
    #pragma unroll
    for (int i = 0; i < R; i++) {
        int n = q + i * 16;
        if (n < N) {
            float v = g_item[(ROW0 + n) * 64 + j];
            s += v;
            ss += v * v;
        }
    }
    red[tid] = make_float2(s, ss);
    __syncthreads();
    if (tid < 64) {
        float S = 0.f, SS = 0.f;
        #pragma unroll
        for (int k = 0; k < 16; k++) {
            float2 r = red[tid + 64 * k];
            S += r.x; SS += r.y;
        }
        float m = S / (float)N;
        float var = (SS - (float)N * m * m) / (float)(N - 1);
        g_stat[SBASE + tid] = m;
        g_stat[SBASE + 64 + tid] = rsqrtf(var);
    }
}

__global__ void __launch_bounds__(1024) k_stats() {
    __shared__ float2 red[1024];
    if (blockIdx.x == 0) stats_body<0, CELL_N, 0>(red);
    else                 stats_body<CELL_N, DRUG_N, 128>(red);
}

// ---------------- interact + agg fused (normalize query on the fly) ----------------
#define IA_ROWS (128 * 65)
__global__ void __launch_bounds__(256) k_interagg(
        const int* __restrict__ cell_nbr, const int* __restrict__ drug_nbr,
        const float* __restrict__ table,
        const float* __restrict__ W, const float* __restrict__ b,
        const float* __restrict__ combw) {
    int n = blockIdx.x;
    const int* nbr;
    int sbase;
    if (n < CELL_N) { nbr = cell_nbr + n * 256; sbase = 0; }
    else { nbr = drug_nbr + (n - CELL_N) * 256; sbase = 128; }

    extern __shared__ float sm[];
    float* rows = sm;                      // 2 * IA_ROWS
    float* it   = sm + 2 * IA_ROWS;        // 64
    float* sc   = it + 64;                 // 256
    float* xr   = sc + 256;                // 128
    float* wred = xr + 128;                // 16
    float* part = wred + 16;               // 256
    __shared__ int idxs[256];

    int tid = threadIdx.x;
    int warp = tid >> 5, lane = tid & 31;
    int hop = tid >> 7, wg = tid & 127;
    idxs[tid] = nbr[tid];
    if (tid < 64)
        it[tid] = (g_item[n * 64 + tid] - g_stat[sbase + tid]) * g_stat[sbase + 64 + tid];
    __syncthreads();
    const float4* t4 = (const float4*)table;
    for (int e = tid; e < 2 * 128 * 16; e += 256) {
        int hk = e >> 4, q = e & 15;
        int h = hk >> 7, k = hk & 127;
        float4 v = t4[idxs[h * 128 + k] * 16 + q];
        float* dst = &rows[h * IA_ROWS + k * 65 + q * 4];
        dst[0] = v.x; dst[1] = v.y; dst[2] = v.z; dst[3] = v.w;
    }
    __syncthreads();
    const float* myrow = &rows[hop * IA_ROWS + wg * 65];
    float s = 0.f;
    #pragma unroll 8
    for (int d = 0; d < 64; d++) s += myrow[d] * it[d];
    float m = s;
    #pragma unroll
    for (int o = 16; o; o >>= 1) m = fmaxf(m, __shfl_xor_sync(0xffffffffu, m, o));
    if (lane == 0) wred[warp] = m;
    __syncthreads();
    int wb = (hop << 2);
    float mx = fmaxf(fmaxf(wred[wb], wred[wb + 1]), fmaxf(wred[wb + 2], wred[wb + 3]));
    float e = expf(s - mx);
    sc[tid] = e;
    float t = e;
    #pragma unroll
    for (int o = 16; o; o >>= 1) t += __shfl_xor_sync(0xffffffffu, t, o);
    if (lane == 0) wred[8 + warp] = t;
    __syncthreads();
    float inv = 1.f / (wred[8 + wb] + wred[9 + wb] + wred[10 + wb] + wred[11 + wb]);
    int d = wg & 63, kh = wg >> 6;
    const float* rb = &rows[hop * IA_ROWS + (kh * 64) * 65];
    const float* sb = &sc[hop * 128 + kh * 64];
    float o = 0.f;
    #pragma unroll 8
    for (int k2 = 0; k2 < 64; k2++) o += sb[k2] * rb[k2 * 65 + d];
    part[tid] = o;
    __syncthreads();
    if (wg < 64) {
        int base = hop << 7;
        xr[hop * 64 + wg] = (part[base + wg] + part[base + 64 + wg]) * inv;
    }
    __syncthreads();
    int j = tid & 63, sl = tid >> 6;
    float ag = 0.f;
    const float* wrow = &W[j * 128 + sl * 32];
    const float* xs = &xr[sl * 32];
    #pragma unroll 8
    for (int t2 = 0; t2 < 32; t2++) ag += wrow[t2] * xs[t2];
    part[tid] = ag;
    __syncthreads();
    if (tid < 64) {
        float v = part[tid] + part[tid + 64] + part[tid + 128] + part[tid + 192] + b[tid];
        g_emb[n * 64 + tid] = v;
        it[tid] = v;
        sc[tid] = v * v;
    }
    __syncthreads();
    if (tid < 32) {
        float v = sc[tid] + sc[tid + 32];
        #pragma unroll
        for (int o2 = 16; o2; o2 >>= 1) v += __shfl_down_sync(0xffffffffu, v, o2);
        if (tid == 0) g_normsq[n] = v;
    }
    if (n < CELL_N && tid < 128) {
        float s2 = 0.f;
        #pragma unroll 8
        for (int j2 = 0; j2 < 64; j2++) s2 += combw[j2 * 128 + tid] * it[j2];
        g_U[n * 128 + tid] = s2;
    }
}

// ---------------- score (blocks 0..15, float4) + loss (block 16) ----------------
__global__ void __launch_bounds__(256) k_scoreloss(
        const int* __restrict__ data, const int* __restrict__ cell_nbr,
        const int* __restrict__ drug_nbr, float* __restrict__ out, int loss_idx) {
    int blk = blockIdx.x;
    int tid = threadIdx.x;
    if (blk < 16) {
        int bidx = blk * 256 + tid;
        int c  = data[3 * bidx];
        int d1 = data[3 * bidx + 1];
        int d2 = data[3 * bidx + 2];
        const float4* e1 = (const float4*)(g_emb + (CELL_N + d1) * 64);
        const float4* e2 = (const float4*)(g_emb + (CELL_N + d2) * 64);
        const float4* u  = (const float4*)(g_U + c * 128);
        float s = 0.f;
        #pragma unroll
        for (int t = 0; t < 16; t++) {
            float4 a = e1[t], bb = e2[t], u0 = u[t], u1 = u[16 + t];
            s += a.x * u0.x + a.y * u0.y + a.z * u0.z + a.w * u0.w;
            s += bb.x * u1.x + bb.y * u1.y + bb.z * u1.z + bb.w * u1.w;
            s -= a.x * bb.x + a.y * bb.y + a.z * bb.z + a.w * bb.w;
        }
        out[bidx] = s;
        return;
    }
    __shared__ float nsq[TOT_N];
    __shared__ float red[256];
    for (int i = tid; i < TOT_N; i += 256) nsq[i] = g_normsq[i];
    __syncthreads();
    float ir = 0.f;
    for (int bidx = tid; bidx < BATCH; bidx += 256) {
        int c  = data[3 * bidx];
        int d1 = data[3 * bidx + 1];
        int d2 = data[3 * bidx + 2];
        ir += nsq[c] + nsq[CELL_N + d1] + nsq[CELL_N + d2];
    }
    float nr = 0.f;
    for (int e = tid; e < 1536; e += 256) {
        int set = e >> 8, off = e & 255;
        int hop = set / 3, which = set - hop * 3;
        int nodeidx = data[hop * 3 + which];
        int p = (which == 0) ? cell_nbr[nodeidx * 256 + off] : drug_nbr[nodeidx * 256 + off];
        nr += g_tablesq[p];
    }
    red[tid] = 0.5f * ir + 0.5f * nr;
    __syncthreads();
    #pragma unroll
    for (int off = 128; off; off >>= 1) {
        if (tid < off) red[tid] += red[tid + off];
        __syncthreads();
    }
    if (tid == 0) out[loss_idx] = 1e-6f * red[0] / (float)BATCH;
}

// ---------------- launch ----------------
extern "C" void kernel_launch(void* const* d_in, const int* in_sizes, int n_in,
                              void* d_out, int out_size) {
    const int*   data     = (const int*)  d_in[0];
    const int*   cell_nbr = (const int*)  d_in[1];
    const int*   drug_nbr = (const int*)  d_in[2];
    const float* table    = (const float*)d_in[3];
    const float* cell_pre = (const float*)d_in[4];
    const float* drug_pre = (const float*)d_in[5];
    const float* c1w      = (const float*)d_in[6];
    const float* c1b      = (const float*)d_in[7];
    const float* c2w      = (const float*)d_in[8];
    const float* c2b      = (const float*)d_in[9];
    const float* ow       = (const float*)d_in[10];
    const float* ob       = (const float*)d_in[11];
    const float* aw       = (const float*)d_in[12];
    const float* ab       = (const float*)d_in[13];
    const float* cw       = (const float*)d_in[14];
    float* out = (float*)d_out;

    int ia_smem = (2 * IA_ROWS + 64 + 256 + 128 + 16 + 256) * 4;
    cudaFuncSetAttribute(k_interagg, cudaFuncAttributeMaxDynamicSharedMemorySize, ia_smem);

    k_conv1<<<TSQ_N + TOT_N * 2, 256>>>(cell_pre, drug_pre, c1w, c1b, table);
    k_conv2<<<TOT_N * 2, 256>>>(c2w, c2b);

    dim3 fcg(27, KSPLIT);
    k_fc<<<fcg, 256>>>(ow);
    k_fcred<<<(TOT_N * 16 + 255) / 256, 256>>>(ob);
    k_stats<<<2, 1024>>>();

    k_interagg<<<TOT_N, 256, ia_smem>>>(cell_nbr, drug_nbr, table, aw, ab, cw);
    k_scoreloss<<<17, 256>>>(data, cell_nbr, drug_nbr, out, out_size - 1);
}

// round 12
// speedup vs baseline: 1.1485x; 1.1485x over previous
#include <cuda_runtime.h>

#define CELL_N 76
#define DRUG_N 764
#define TOT_N  840
#define BATCH  4096
#define NPROT  15970
#define KSPLIT 8
#define KCHUNK 1024  // 8192 / KSPLIT
#define TSQ_N  ((NPROT + 7) / 8)   // 1997 tablesq blocks

// ---------------- scratch (device globals; no allocs allowed) ----------------
__device__ float g_pool1[TOT_N * 4 * 64 * 64];
__device__ float g_pool2[TOT_N * 8 * 32 * 32];
__device__ float g_fcp  [KSPLIT * TOT_N * 64];
__device__ float g_item [TOT_N * 64];
__device__ float g_stat [4 * 64];          // [mean_c, inv_c, mean_d, inv_d]
__device__ float g_emb  [TOT_N * 64];
__device__ float g_normsq[TOT_N];
__device__ float g_U    [CELL_N * 128];
__device__ float g_tablesq[NPROT];

// ---------------- tablesq (blocks first) + conv1 (merged cell+drug) ----------------
// conv1 weights windowed from smem: 9 live weight regs -> 5 CTAs/SM (R10 proven).
__global__ void __launch_bounds__(256, 5) k_conv1(
        const float* __restrict__ cell_pre, const float* __restrict__ drug_pre,
        const float* __restrict__ w, const float* __restrict__ b,
        const float* __restrict__ table) {
    int blk = blockIdx.x;
    int tid = threadIdx.x;
    if (blk < TSQ_N) {
        int warp = blk * 8 + (tid >> 5);
        int lane = tid & 31;
        if (warp >= NPROT) return;
        const float* r = table + warp * 64;
        float a = r[lane], bb = r[lane + 32];
        float s = a * a + bb * bb;
        #pragma unroll
        for (int o = 16; o; o >>= 1) s += __shfl_down_sync(0xffffffffu, s, o);
        if (lane == 0) g_tablesq[warp] = s;
        return;
    }
    int cblk = blk - TSQ_N;
    int half = cblk & 1;
    int gn;
    const float* x;
    if (cblk < 2 * CELL_N) { gn = cblk >> 1; x = cell_pre + gn * 16384; }
    else { int n = (cblk - 2 * CELL_N) >> 1; gn = CELL_N + n; x = drug_pre + n * 16384; }
    __shared__ float tile[66 * 130];
    __shared__ float ws1[36];
    __shared__ float bs1[4];
    if (tid < 36) ws1[tid] = w[tid];
    if (tid < 4)  bs1[tid] = b[tid];
    int row0 = half * 64 - 1;
    for (int idx = tid; idx < 66 * 130; idx += 256) {
        int r = idx / 130, c = idx - r * 130;
        int y = row0 + r, xx = c - 1;
        tile[idx] = (y >= 0 && y < 128 && (unsigned)xx < 128u) ? x[y * 128 + xx] : 0.f;
    }
    __syncthreads();
    #pragma unroll
    for (int i = 0; i < 8; i++) {
        int pos = tid + i * 256;
        int oy = pos >> 6, ox = pos & 63;
        float p[4][4];
        #pragma unroll
        for (int r = 0; r < 4; r++) {
            const float2* s = (const float2*)&tile[(2 * oy + r) * 130 + 2 * ox];
            float2 a = s[0], d = s[1];
            p[r][0] = a.x; p[r][1] = a.y; p[r][2] = d.x; p[r][3] = d.y;
        }
        #pragma unroll
        for (int oc = 0; oc < 4; oc++) {
            float wr[9];
            #pragma unroll
            for (int t = 0; t < 9; t++) wr[t] = ws1[oc * 9 + t];
            float bv = bs1[oc];
            float q00 = bv, q01 = bv, q10 = bv, q11 = bv;
            #pragma unroll
            for (int dy = 0; dy < 3; dy++)
            #pragma unroll
            for (int dx = 0; dx < 3; dx++) {
                float wv = wr[dy * 3 + dx];
                q00 += p[dy    ][dx    ] * wv;
                q01 += p[dy    ][dx + 1] * wv;
                q10 += p[dy + 1][dx    ] * wv;
                q11 += p[dy + 1][dx + 1] * wv;
            }
            float m = fmaxf(fmaxf(q00, q01), fmaxf(q10, q11));
            g_pool1[((gn * 4 + oc) * 64 + half * 32 + oy) * 64 + ox] = fmaxf(m, 0.f);
        }
    }
}

// ---------------- conv2 (4->8) + relu + pool, weight window -> 4 CTAs/SM (R10 proven) ----------------
#define C2_STR 68
#define C2_CH  (34 * C2_STR)
__global__ void __launch_bounds__(256, 4) k_conv2(
        const float* __restrict__ w, const float* __restrict__ b) {
    int n = blockIdx.x >> 1, half = blockIdx.x & 1;
    __shared__ float tile[4 * C2_CH];
    __shared__ float ws[288];
    int tid = threadIdx.x;
    int row0 = half * 32 - 1;
    for (int i = tid; i < 288; i += 256) ws[i] = w[i];
    for (int idx = tid; idx < 4 * 34 * 66; idx += 256) {
        int c = idx / (34 * 66), rem = idx - c * (34 * 66);
        int r = rem / 66, cc = rem - r * 66;
        int y = row0 + r, xx = cc - 1;
        tile[c * C2_CH + r * C2_STR + cc] =
            ((unsigned)y < 64u && (unsigned)xx < 64u)
          ? g_pool1[((n * 4 + c) * 64 + y) * 64 + xx] : 0.f;
    }
    __syncthreads();
    int oc = tid >> 5, lane = tid & 31;
    float bs = b[oc];
    #pragma unroll
    for (int i = 0; i < 8; i++) {
        int pos = lane + i * 32;
        int oy = pos >> 4, oxp = pos & 15;
        float q[8];
        #pragma unroll
        for (int k = 0; k < 8; k++) q[k] = bs;
        #pragma unroll
        for (int c = 0; c < 4; c++) {
            float pt[4][6];
            #pragma unroll
            for (int rr = 0; rr < 4; rr++) {
                const float* base = &tile[c * C2_CH + (2 * oy + rr) * C2_STR + 4 * oxp];
                float4 a = *(const float4*)base;
                float2 b2 = *(const float2*)(base + 4);
                pt[rr][0] = a.x; pt[rr][1] = a.y; pt[rr][2] = a.z;
                pt[rr][3] = a.w; pt[rr][4] = b2.x; pt[rr][5] = b2.y;
            }
            float wr[9];
            #pragma unroll
            for (int t = 0; t < 9; t++) wr[t] = ws[oc * 36 + c * 9 + t];
            #pragma unroll
            for (int dy = 0; dy < 3; dy++)
            #pragma unroll
            for (int dx = 0; dx < 3; dx++) {
                float wv = wr[dy * 3 + dx];
                q[0] += pt[dy    ][dx    ] * wv;
                q[1] += pt[dy    ][dx + 1] * wv;
                q[2] += pt[dy + 1][dx    ] * wv;
                q[3] += pt[dy + 1][dx + 1] * wv;
                q[4] += pt[dy    ][dx + 2] * wv;
                q[5] += pt[dy    ][dx + 3] * wv;
                q[6] += pt[dy + 1][dx + 2] * wv;
                q[7] += pt[dy + 1][dx + 3] * wv;
            }
        }
        float m0 = fmaxf(fmaxf(q[0], q[1]), fmaxf(q[2], q[3]));
        float m1 = fmaxf(fmaxf(q[4], q[5]), fmaxf(q[6], q[7]));
        float2 v = make_float2(fmaxf(m0, 0.f), fmaxf(m1, 0.f));
        *(float2*)&g_pool2[((n * 8 + oc) * 32 + half * 16 + oy) * 32 + 2 * oxp] = v;
    }
}

// ---------------- FC as tiled GEMM with K-split ----------------
__global__ void __launch_bounds__(256) k_fc(const float* __restrict__ W) {
    int m0 = blockIdx.x * 32;
    int kb = blockIdx.y;
    int k0 = kb * KCHUNK;
    __shared__ float Xs[32][64];
    __shared__ float Ws[64][68];
    int tid = threadIdx.x;
    int tm = tid >> 5, tn = tid & 31;
    float acc[4][2] = {};
    for (int kt = 0; kt < KCHUNK; kt += 64) {
        #pragma unroll
        for (int i = 0; i < 8; i++) {
            int idx = tid + i * 256;
            int r = idx >> 6, c = idx & 63;
            int m = m0 + r;
            Xs[r][c] = (m < TOT_N) ? g_pool2[m * 8192 + k0 + kt + c] : 0.f;
        }
        #pragma unroll
        for (int i = 0; i < 16; i++) {
            int idx = tid + i * 256;
            int j = idx >> 6, c = idx & 63;
            Ws[j][c] = W[j * 8192 + k0 + kt + c];
        }
        __syncthreads();
        #pragma unroll
        for (int kk = 0; kk < 64; kk += 4) {
            float4 w0 = *(const float4*)&Ws[tn     ][kk];
            float4 w1 = *(const float4*)&Ws[tn + 32][kk];
            #pragma unroll
            for (int r = 0; r < 4; r++) {
                float4 xv = *(const float4*)&Xs[tm * 4 + r][kk];
                acc[r][0] += xv.x * w0.x + xv.y * w0.y + xv.z * w0.z + xv.w * w0.w;
                acc[r][1] += xv.x * w1.x + xv.y * w1.y + xv.z * w1.z + xv.w * w1.w;
            }
        }
        __syncthreads();
    }
    #pragma unroll
    for (int r = 0; r < 4; r++) {
        int m = m0 + tm * 4 + r;
        if (m < TOT_N) {
            g_fcp[(kb * TOT_N + m) * 64 + tn     ] = acc[r][0];
            g_fcp[(kb * TOT_N + m) * 64 + tn + 32] = acc[r][1];
        }
    }
}

// ---------------- reduce K-split partials + bias -> g_item (float4) ----------------
__global__ void k_fcred(const float* __restrict__ b) {
    int v = blockIdx.x * blockDim.x + threadIdx.x;     // float4 index
    if (v >= TOT_N * 16) return;
    int j4 = (v & 15) * 4;
    float4 s = *(const float4*)&b[j4];
    #pragma unroll
    for (int kb = 0; kb < KSPLIT; kb++) {
        float4 p = *(const float4*)&g_fcp[kb * TOT_N * 64 + v * 4];
        s.x += p.x; s.y += p.y; s.z += p.z; s.w += p.w;
    }
    *(float4*)&g_item[v * 4] = s;
}

// ---------------- stats only: mean + rsqrt(var) per feature per group ----------------
template<int ROW0, int N, int SBASE>
__device__ __forceinline__ void stats_body(float2* red) {
    int tid = threadIdx.x;
    int j = tid & 63, q = tid >> 6;
    constexpr int R = (N + 15) / 16;
    float s = 0.f, ss = 0.f;
    #pragma unroll
    for (int i = 0; i < R; i++) {
        int n = q + i * 16;
        if (n < N) {
            float v = g_item[(ROW0 + n) * 64 + j];
            s += v;
            ss += v * v;
        }
    }
    red[tid] = make_float2(s, ss);
    __syncthreads();
    if (tid < 64) {
        float S = 0.f, SS = 0.f;
        #pragma unroll
        for (int k = 0; k < 16; k++) {
            float2 r = red[tid + 64 * k];
            S += r.x; SS += r.y;
        }
        float m = S / (float)N;
        float var = (SS - (float)N * m * m) / (float)(N - 1);
        g_stat[SBASE + tid] = m;
        g_stat[SBASE + 64 + tid] = rsqrtf(var);
    }
}

__global__ void __launch_bounds__(1024) k_stats() {
    __shared__ float2 red[1024];
    if (blockIdx.x == 0) stats_body<0, CELL_N, 0>(red);
    else                 stats_body<CELL_N, DRUG_N, 128>(red);
}

// ---------------- interact + agg fused (normalize query on the fly) ----------------
#define IA_ROWS (128 * 65)
__global__ void __launch_bounds__(256) k_interagg(
        const int* __restrict__ cell_nbr, const int* __restrict__ drug_nbr,
        const float* __restrict__ table,
        const float* __restrict__ W, const float* __restrict__ b,
        const float* __restrict__ combw) {
    int n = blockIdx.x;
    const int* nbr;
    int sbase;
    if (n < CELL_N) { nbr = cell_nbr + n * 256; sbase = 0; }
    else { nbr = drug_nbr + (n - CELL_N) * 256; sbase = 128; }

    extern __shared__ float sm[];
    float* rows = sm;                      // 2 * IA_ROWS
    float* it   = sm + 2 * IA_ROWS;        // 64
    float* sc   = it + 64;                 // 256
    float* xr   = sc + 256;                // 128
    float* wred = xr + 128;                // 16
    float* part = wred + 16;               // 256
    __shared__ int idxs[256];

    int tid = threadIdx.x;
    int warp = tid >> 5, lane = tid & 31;
    int hop = tid >> 7, wg = tid & 127;
    idxs[tid] = nbr[tid];
    if (tid < 64)
        it[tid] = (g_item[n * 64 + tid] - g_stat[sbase + tid]) * g_stat[sbase + 64 + tid];
    __syncthreads();
    const float4* t4 = (const float4*)table;
    for (int e = tid; e < 2 * 128 * 16; e += 256) {
        int hk = e >> 4, q = e & 15;
        int h = hk >> 7, k = hk & 127;
        float4 v = t4[idxs[h * 128 + k] * 16 + q];
        float* dst = &rows[h * IA_ROWS + k * 65 + q * 4];
        dst[0] = v.x; dst[1] = v.y; dst[2] = v.z; dst[3] = v.w;
    }
    __syncthreads();
    const float* myrow = &rows[hop * IA_ROWS + wg * 65];
    float s = 0.f;
    #pragma unroll 8
    for (int d = 0; d < 64; d++) s += myrow[d] * it[d];
    float m = s;
    #pragma unroll
    for (int o = 16; o; o >>= 1) m = fmaxf(m, __shfl_xor_sync(0xffffffffu, m, o));
    if (lane == 0) wred[warp] = m;
    __syncthreads();
    int wb = (hop << 2);
    float mx = fmaxf(fmaxf(wred[wb], wred[wb + 1]), fmaxf(wred[wb + 2], wred[wb + 3]));
    float e = expf(s - mx);
    sc[tid] = e;
    float t = e;
    #pragma unroll
    for (int o = 16; o; o >>= 1) t += __shfl_xor_sync(0xffffffffu, t, o);
    if (lane == 0) wred[8 + warp] = t;
    __syncthreads();
    float inv = 1.f / (wred[8 + wb] + wred[9 + wb] + wred[10 + wb] + wred[11 + wb]);
    int d = wg & 63, kh = wg >> 6;
    const float* rb = &rows[hop * IA_ROWS + (kh * 64) * 65];
    const float* sb = &sc[hop * 128 + kh * 64];
    float o = 0.f;
    #pragma unroll 8
    for (int k2 = 0; k2 < 64; k2++) o += sb[k2] * rb[k2 * 65 + d];
    part[tid] = o;
    __syncthreads();
    if (wg < 64) {
        int base = hop << 7;
        xr[hop * 64 + wg] = (part[base + wg] + part[base + 64 + wg]) * inv;
    }
    __syncthreads();
    int j = tid & 63, sl = tid >> 6;
    float ag = 0.f;
    const float* wrow = &W[j * 128 + sl * 32];
    const float* xs = &xr[sl * 32];
    #pragma unroll 8
    for (int t2 = 0; t2 < 32; t2++) ag += wrow[t2] * xs[t2];
    part[tid] = ag;
    __syncthreads();
    if (tid < 64) {
        float v = part[tid] + part[tid + 64] + part[tid + 128] + part[tid + 192] + b[tid];
        g_emb[n * 64 + tid] = v;
        it[tid] = v;
        sc[tid] = v * v;
    }
    __syncthreads();
    if (tid < 32) {
        float v = sc[tid] + sc[tid + 32];
        #pragma unroll
        for (int o2 = 16; o2; o2 >>= 1) v += __shfl_down_sync(0xffffffffu, v, o2);
        if (tid == 0) g_normsq[n] = v;
    }
    if (n < CELL_N && tid < 128) {
        float s2 = 0.f;
        #pragma unroll 8
        for (int j2 = 0; j2 < 64; j2++) s2 += combw[j2 * 128 + tid] * it[j2];
        g_U[n * 128 + tid] = s2;
    }
}

// ---------------- score (blocks 0..15, float4) + loss (block 16) ----------------
__global__ void __launch_bounds__(256) k_scoreloss(
        const int* __restrict__ data, const int* __restrict__ cell_nbr,
        const int* __restrict__ drug_nbr, float* __restrict__ out, int loss_idx) {
    int blk = blockIdx.x;
    int tid = threadIdx.x;
    if (blk < 16) {
        int bidx = blk * 256 + tid;
        int c  = data[3 * bidx];
        int d1 = data[3 * bidx + 1];
        int d2 = data[3 * bidx + 2];
        const float4* e1 = (const float4*)(g_emb + (CELL_N + d1) * 64);
        const float4* e2 = (const float4*)(g_emb + (CELL_N + d2) * 64);
        const float4* u  = (const float4*)(g_U + c * 128);
        float s = 0.f;
        #pragma unroll
        for (int t = 0; t < 16; t++) {
            float4 a = e1[t], bb = e2[t], u0 = u[t], u1 = u[16 + t];
            s += a.x * u0.x + a.y * u0.y + a.z * u0.z + a.w * u0.w;
            s += bb.x * u1.x + bb.y * u1.y + bb.z * u1.z + bb.w * u1.w;
            s -= a.x * bb.x + a.y * bb.y + a.z * bb.z + a.w * bb.w;
        }
        out[bidx] = s;
        return;
    }
    __shared__ float nsq[TOT_N];
    __shared__ float red[256];
    for (int i = tid; i < TOT_N; i += 256) nsq[i] = g_normsq[i];
    __syncthreads();
    float ir = 0.f;
    for (int bidx = tid; bidx < BATCH; bidx += 256) {
        int c  = data[3 * bidx];
        int d1 = data[3 * bidx + 1];
        int d2 = data[3 * bidx + 2];
        ir += nsq[c] + nsq[CELL_N + d1] + nsq[CELL_N + d2];
    }
    float nr = 0.f;
    for (int e = tid; e < 1536; e += 256) {
        int set = e >> 8, off = e & 255;
        int hop = set / 3, which = set - hop * 3;
        int nodeidx = data[hop * 3 + which];
        int p = (which == 0) ? cell_nbr[nodeidx * 256 + off] : drug_nbr[nodeidx * 256 + off];
        nr += g_tablesq[p];
    }
    red[tid] = 0.5f * ir + 0.5f * nr;
    __syncthreads();
    #pragma unroll
    for (int off = 128; off; off >>= 1) {
        if (tid < off) red[tid] += red[tid + off];
        __syncthreads();
    }
    if (tid == 0) out[loss_idx] = 1e-6f * red[0] / (float)BATCH;
}

// ---------------- launch ----------------
extern "C" void kernel_launch(void* const* d_in, const int* in_sizes, int n_in,
                              void* d_out, int out_size) {
    const int*   data     = (const int*)  d_in[0];
    const int*   cell_nbr = (const int*)  d_in[1];
    const int*   drug_nbr = (const int*)  d_in[2];
    const float* table    = (const float*)d_in[3];
    const float* cell_pre = (const float*)d_in[4];
    const float* drug_pre = (const float*)d_in[5];
    const float* c1w      = (const float*)d_in[6];
    const float* c1b      = (const float*)d_in[7];
    const float* c2w      = (const float*)d_in[8];
    const float* c2b      = (const float*)d_in[9];
    const float* ow       = (const float*)d_in[10];
    const float* ob       = (const float*)d_in[11];
    const float* aw       = (const float*)d_in[12];
    const float* ab       = (const float*)d_in[13];
    const float* cw       = (const float*)d_in[14];
    float* out = (float*)d_out;

    int ia_smem = (2 * IA_ROWS + 64 + 256 + 128 + 16 + 256) * 4;
    cudaFuncSetAttribute(k_interagg, cudaFuncAttributeMaxDynamicSharedMemorySize, ia_smem);

    k_conv1<<<TSQ_N + TOT_N * 2, 256>>>(cell_pre, drug_pre, c1w, c1b, table);
    k_conv2<<<TOT_N * 2, 256>>>(c2w, c2b);

    dim3 fcg(27, KSPLIT);
    k_fc<<<fcg, 256>>>(ow);
    k_fcred<<<(TOT_N * 16 + 255) / 256, 256>>>(ob);
    k_stats<<<2, 1024>>>();

    k_interagg<<<TOT_N, 256, ia_smem>>>(cell_nbr, drug_nbr, table, aw, ab, cw);
    k_scoreloss<<<17, 256>>>(data, cell_nbr, drug_nbr, out, out_size - 1);
}

// round 13
// speedup vs baseline: 1.1761x; 1.0241x over previous
#include <cuda_runtime.h>

#define CELL_N 76
#define DRUG_N 764
#define TOT_N  840
#define BATCH  4096
#define NPROT  15970
#define KSPLIT 8
#define KCHUNK 1024  // 8192 / KSPLIT
#define TSQ_N  ((NPROT + 7) / 8)   // 1997 tablesq blocks

// ---------------- scratch (device globals; no allocs allowed) ----------------
__device__ float g_pool1[TOT_N * 4 * 64 * 64];
__device__ float g_pool2[TOT_N * 8 * 32 * 32];
__device__ float g_fcp  [KSPLIT * TOT_N * 64];
__device__ float g_item [TOT_N * 64];
__device__ float g_stat [4 * 64];          // [mean_c, inv_c, mean_d, inv_d]
__device__ float g_emb  [TOT_N * 64];
__device__ float g_normsq[TOT_N];
__device__ float g_U    [CELL_N * 128];
__device__ float g_tablesq[NPROT];

// ---------------- tablesq (blocks first) + conv1 (merged cell+drug) ----------------
// conv1 compute: conv2-style fixed-oc pair-blocking. Weights loaded ONCE per
// thread (9 regs); 16 pooled-output pairs each: 8 LDS + 72 FFMA per pair.
#define C1_STR 132
__global__ void __launch_bounds__(256, 4) k_conv1(
        const float* __restrict__ cell_pre, const float* __restrict__ drug_pre,
        const float* __restrict__ w, const float* __restrict__ b,
        const float* __restrict__ table) {
    int blk = blockIdx.x;
    int tid = threadIdx.x;
    if (blk < TSQ_N) {
        int warp = blk * 8 + (tid >> 5);
        int lane = tid & 31;
        if (warp >= NPROT) return;
        const float* r = table + warp * 64;
        float a = r[lane], bb = r[lane + 32];
        float s = a * a + bb * bb;
        #pragma unroll
        for (int o = 16; o; o >>= 1) s += __shfl_down_sync(0xffffffffu, s, o);
        if (lane == 0) g_tablesq[warp] = s;
        return;
    }
    int cblk = blk - TSQ_N;
    int half = cblk & 1;
    int gn;
    const float* x;
    if (cblk < 2 * CELL_N) { gn = cblk >> 1; x = cell_pre + gn * 16384; }
    else { int n = (cblk - 2 * CELL_N) >> 1; gn = CELL_N + n; x = drug_pre + n * 16384; }
    __shared__ float tile[66 * C1_STR];
    __shared__ float ws1[36];
    __shared__ float bs1[4];
    if (tid < 36) ws1[tid] = w[tid];
    if (tid < 4)  bs1[tid] = b[tid];
    int row0 = half * 64 - 1;
    for (int idx = tid; idx < 66 * C1_STR; idx += 256) {
        int r = idx / C1_STR, c = idx - r * C1_STR;
        int y = row0 + r, xx = c - 1;
        tile[idx] = ((unsigned)y < 128u && (unsigned)xx < 128u) ? x[y * 128 + xx] : 0.f;
    }
    __syncthreads();
    // fixed oc per thread group; 16 output-pairs per thread
    int oc = tid >> 6, t64 = tid & 63;
    float wr[9];
    #pragma unroll
    for (int t = 0; t < 9; t++) wr[t] = ws1[oc * 9 + t];
    float bv = bs1[oc];
    #pragma unroll
    for (int i = 0; i < 16; i++) {
        int pos = t64 + i * 64;              // 1024 pairs per oc
        int oy = pos >> 5, oxp = pos & 31;
        float pt[4][6];
        #pragma unroll
        for (int rr = 0; rr < 4; rr++) {
            const float* base = &tile[(2 * oy + rr) * C1_STR + 4 * oxp];
            float4 a = *(const float4*)base;
            float2 b2 = *(const float2*)(base + 4);
            pt[rr][0] = a.x; pt[rr][1] = a.y; pt[rr][2] = a.z;
            pt[rr][3] = a.w; pt[rr][4] = b2.x; pt[rr][5] = b2.y;
        }
        float q[8];
        #pragma unroll
        for (int k = 0; k < 8; k++) q[k] = bv;
        #pragma unroll
        for (int dy = 0; dy < 3; dy++)
        #pragma unroll
        for (int dx = 0; dx < 3; dx++) {
            float wv = wr[dy * 3 + dx];
            q[0] += pt[dy    ][dx    ] * wv;
            q[1] += pt[dy    ][dx + 1] * wv;
            q[2] += pt[dy + 1][dx    ] * wv;
            q[3] += pt[dy + 1][dx + 1] * wv;
            q[4] += pt[dy    ][dx + 2] * wv;
            q[5] += pt[dy    ][dx + 3] * wv;
            q[6] += pt[dy + 1][dx + 2] * wv;
            q[7] += pt[dy + 1][dx + 3] * wv;
        }
        float m0 = fmaxf(fmaxf(q[0], q[1]), fmaxf(q[2], q[3]));
        float m1 = fmaxf(fmaxf(q[4], q[5]), fmaxf(q[6], q[7]));
        float2 v = make_float2(fmaxf(m0, 0.f), fmaxf(m1, 0.f));
        *(float2*)&g_pool1[((gn * 4 + oc) * 64 + half * 32 + oy) * 64 + 2 * oxp] = v;
    }
}

// ---------------- conv2 (4->8) + relu + pool, weight window -> 4 CTAs/SM (R10 proven) ----------------
#define C2_STR 68
#define C2_CH  (34 * C2_STR)
__global__ void __launch_bounds__(256, 4) k_conv2(
        const float* __restrict__ w, const float* __restrict__ b) {
    int n = blockIdx.x >> 1, half = blockIdx.x & 1;
    __shared__ float tile[4 * C2_CH];
    __shared__ float ws[288];
    int tid = threadIdx.x;
    int row0 = half * 32 - 1;
    for (int i = tid; i < 288; i += 256) ws[i] = w[i];
    for (int idx = tid; idx < 4 * 34 * 66; idx += 256) {
        int c = idx / (34 * 66), rem = idx - c * (34 * 66);
        int r = rem / 66, cc = rem - r * 66;
        int y = row0 + r, xx = cc - 1;
        tile[c * C2_CH + r * C2_STR + cc] =
            ((unsigned)y < 64u && (unsigned)xx < 64u)
          ? g_pool1[((n * 4 + c) * 64 + y) * 64 + xx] : 0.f;
    }
    __syncthreads();
    int oc = tid >> 5, lane = tid & 31;
    float bs = b[oc];
    #pragma unroll
    for (int i = 0; i < 8; i++) {
        int pos = lane + i * 32;
        int oy = pos >> 4, oxp = pos & 15;
        float q[8];
        #pragma unroll
        for (int k = 0; k < 8; k++) q[k] = bs;
        #pragma unroll
        for (int c = 0; c < 4; c++) {
            float pt[4][6];
            #pragma unroll
            for (int rr = 0; rr < 4; rr++) {
                const float* base = &tile[c * C2_CH + (2 * oy + rr) * C2_STR + 4 * oxp];
                float4 a = *(const float4*)base;
                float2 b2 = *(const float2*)(base + 4);
                pt[rr][0] = a.x; pt[rr][1] = a.y; pt[rr][2] = a.z;
                pt[rr][3] = a.w; pt[rr][4] = b2.x; pt[rr][5] = b2.y;
            }
            float wr[9];
            #pragma unroll
            for (int t = 0; t < 9; t++) wr[t] = ws[oc * 36 + c * 9 + t];
            #pragma unroll
            for (int dy = 0; dy < 3; dy++)
            #pragma unroll
            for (int dx = 0; dx < 3; dx++) {
                float wv = wr[dy * 3 + dx];
                q[0] += pt[dy    ][dx    ] * wv;
                q[1] += pt[dy    ][dx + 1] * wv;
                q[2] += pt[dy + 1][dx    ] * wv;
                q[3] += pt[dy + 1][dx + 1] * wv;
                q[4] += pt[dy    ][dx + 2] * wv;
                q[5] += pt[dy    ][dx + 3] * wv;
                q[6] += pt[dy + 1][dx + 2] * wv;
                q[7] += pt[dy + 1][dx + 3] * wv;
            }
        }
        float m0 = fmaxf(fmaxf(q[0], q[1]), fmaxf(q[2], q[3]));
        float m1 = fmaxf(fmaxf(q[4], q[5]), fmaxf(q[6], q[7]));
        float2 v = make_float2(fmaxf(m0, 0.f), fmaxf(m1, 0.f));
        *(float2*)&g_pool2[((n * 8 + oc) * 32 + half * 16 + oy) * 32 + 2 * oxp] = v;
    }
}

// ---------------- FC as tiled GEMM with K-split ----------------
__global__ void __launch_bounds__(256) k_fc(const float* __restrict__ W) {
    int m0 = blockIdx.x * 32;
    int kb = blockIdx.y;
    int k0 = kb * KCHUNK;
    __shared__ float Xs[32][64];
    __shared__ float Ws[64][68];
    int tid = threadIdx.x;
    int tm = tid >> 5, tn = tid & 31;
    float acc[4][2] = {};
    for (int kt = 0; kt < KCHUNK; kt += 64) {
        #pragma unroll
        for (int i = 0; i < 8; i++) {
            int idx = tid + i * 256;
            int r = idx >> 6, c = idx & 63;
            int m = m0 + r;
            Xs[r][c] = (m < TOT_N) ? g_pool2[m * 8192 + k0 + kt + c] : 0.f;
        }
        #pragma unroll
        for (int i = 0; i < 16; i++) {
            int idx = tid + i * 256;
            int j = idx >> 6, c = idx & 63;
            Ws[j][c] = W[j * 8192 + k0 + kt + c];
        }
        __syncthreads();
        #pragma unroll
        for (int kk = 0; kk < 64; kk += 4) {
            float4 w0 = *(const float4*)&Ws[tn     ][kk];
            float4 w1 = *(const float4*)&Ws[tn + 32][kk];
            #pragma unroll
            for (int r = 0; r < 4; r++) {
                float4 xv = *(const float4*)&Xs[tm * 4 + r][kk];
                acc[r][0] += xv.x * w0.x + xv.y * w0.y + xv.z * w0.z + xv.w * w0.w;
                acc[r][1] += xv.x * w1.x + xv.y * w1.y + xv.z * w1.z + xv.w * w1.w;
            }
        }
        __syncthreads();
    }
    #pragma unroll
    for (int r = 0; r < 4; r++) {
        int m = m0 + tm * 4 + r;
        if (m < TOT_N) {
            g_fcp[(kb * TOT_N + m) * 64 + tn     ] = acc[r][0];
            g_fcp[(kb * TOT_N + m) * 64 + tn + 32] = acc[r][1];
        }
    }
}

// ---------------- reduce K-split partials + bias -> g_item (float4) ----------------
__global__ void k_fcred(const float* __restrict__ b) {
    int v = blockIdx.x * blockDim.x + threadIdx.x;     // float4 index
    if (v >= TOT_N * 16) return;
    int j4 = (v & 15) * 4;
    float4 s = *(const float4*)&b[j4];
    #pragma unroll
    for (int kb = 0; kb < KSPLIT; kb++) {
        float4 p = *(const float4*)&g_fcp[kb * TOT_N * 64 + v * 4];
        s.x += p.x; s.y += p.y; s.z += p.z; s.w += p.w;
    }
    *(float4*)&g_item[v * 4] = s;
}

// ---------------- stats only: mean + rsqrt(var) per feature per group ----------------
template<int ROW0, int N, int SBASE>
__device__ __forceinline__ void stats_body(float2* red) {
    int tid = threadIdx.x;
    int j = tid & 63, q = tid >> 6;
    constexpr int R = (N + 15) / 16;
    float s = 0.f, ss = 0.f;
    #pragma unroll
    for (int i = 0; i < R; i++) {
        int n = q + i * 16;
        if (n < N) {
            float v = g_item[(ROW0 + n) * 64 + j];
            s += v;
            ss += v * v;
        }
    }
    red[tid] = make_float2(s, ss);
    __syncthreads();
    if (tid < 64) {
        float S = 0.f, SS = 0.f;
        #pragma unroll
        for (int k = 0; k < 16; k++) {
            float2 r = red[tid + 64 * k];
            S += r.x; SS += r.y;
        }
        float m = S / (float)N;
        float var = (SS - (float)N * m * m) / (float)(N - 1);
        g_stat[SBASE + tid] = m;
        g_stat[SBASE + 64 + tid] = rsqrtf(var);
    }
}

__global__ void __launch_bounds__(1024) k_stats() {
    __shared__ float2 red[1024];
    if (blockIdx.x == 0) stats_body<0, CELL_N, 0>(red);
    else                 stats_body<CELL_N, DRUG_N, 128>(red);
}

// ---------------- interact + agg fused (normalize query on the fly) ----------------
#define IA_ROWS (128 * 65)
__global__ void __launch_bounds__(256) k_interagg(
        const int* __restrict__ cell_nbr, const int* __restrict__ drug_nbr,
        const float* __restrict__ table,
        const float* __restrict__ W, const float* __restrict__ b,
        const float* __restrict__ combw) {
    int n = blockIdx.x;
    const int* nbr;
    int sbase;
    if (n < CELL_N) { nbr = cell_nbr + n * 256; sbase = 0; }
    else { nbr = drug_nbr + (n - CELL_N) * 256; sbase = 128; }

    extern __shared__ float sm[];
    float* rows = sm;                      // 2 * IA_ROWS
    float* it   = sm + 2 * IA_ROWS;        // 64
    float* sc   = it + 64;                 // 256
    float* xr   = sc + 256;                // 128
    float* wred = xr + 128;                // 16
    float* part = wred + 16;               // 256
    __shared__ int idxs[256];

    int tid = threadIdx.x;
    int warp = tid >> 5, lane = tid & 31;
    int hop = tid >> 7, wg = tid & 127;
    idxs[tid] = nbr[tid];
    if (tid < 64)
        it[tid] = (g_item[n * 64 + tid] - g_stat[sbase + tid]) * g_stat[sbase + 64 + tid];
    __syncthreads();
    const float4* t4 = (const float4*)table;
    for (int e = tid; e < 2 * 128 * 16; e += 256) {
        int hk = e >> 4, q = e & 15;
        int h = hk >> 7, k = hk & 127;
        float4 v = t4[idxs[h * 128 + k] * 16 + q];
        float* dst = &rows[h * IA_ROWS + k * 65 + q * 4];
        dst[0] = v.x; dst[1] = v.y; dst[2] = v.z; dst[3] = v.w;
    }
    __syncthreads();
    const float* myrow = &rows[hop * IA_ROWS + wg * 65];
    float s = 0.f;
    #pragma unroll 8
    for (int d = 0; d < 64; d++) s += myrow[d] * it[d];
    float m = s;
    #pragma unroll
    for (int o = 16; o; o >>= 1) m = fmaxf(m, __shfl_xor_sync(0xffffffffu, m, o));
    if (lane == 0) wred[warp] = m;
    __syncthreads();
    int wb = (hop << 2);
    float mx = fmaxf(fmaxf(wred[wb], wred[wb + 1]), fmaxf(wred[wb + 2], wred[wb + 3]));
    float e = expf(s - mx);
    sc[tid] = e;
    float t = e;
    #pragma unroll
    for (int o = 16; o; o >>= 1) t += __shfl_xor_sync(0xffffffffu, t, o);
    if (lane == 0) wred[8 + warp] = t;
    __syncthreads();
    float inv = 1.f / (wred[8 + wb] + wred[9 + wb] + wred[10 + wb] + wred[11 + wb]);
    int d = wg & 63, kh = wg >> 6;
    const float* rb = &rows[hop * IA_ROWS + (kh * 64) * 65];
    const float* sb = &sc[hop * 128 + kh * 64];
    float o = 0.f;
    #pragma unroll 8
    for (int k2 = 0; k2 < 64; k2++) o += sb[k2] * rb[k2 * 65 + d];
    part[tid] = o;
    __syncthreads();
    if (wg < 64) {
        int base = hop << 7;
        xr[hop * 64 + wg] = (part[base + wg] + part[base + 64 + wg]) * inv;
    }
    __syncthreads();
    int j = tid & 63, sl = tid >> 6;
    float ag = 0.f;
    const float* wrow = &W[j * 128 + sl * 32];
    const float* xs = &xr[sl * 32];
    #pragma unroll 8
    for (int t2 = 0; t2 < 32; t2++) ag += wrow[t2] * xs[t2];
    part[tid] = ag;
    __syncthreads();
    if (tid < 64) {
        float v = part[tid] + part[tid + 64] + part[tid + 128] + part[tid + 192] + b[tid];
        g_emb[n * 64 + tid] = v;
        it[tid] = v;
        sc[tid] = v * v;
    }
    __syncthreads();
    if (tid < 32) {
        float v = sc[tid] + sc[tid + 32];
        #pragma unroll
        for (int o2 = 16; o2; o2 >>= 1) v += __shfl_down_sync(0xffffffffu, v, o2);
        if (tid == 0) g_normsq[n] = v;
    }
    if (n < CELL_N && tid < 128) {
        float s2 = 0.f;
        #pragma unroll 8
        for (int j2 = 0; j2 < 64; j2++) s2 += combw[j2 * 128 + tid] * it[j2];
        g_U[n * 128 + tid] = s2;
    }
}

// ---------------- score (blocks 0..15, float4) + loss (block 16) ----------------
__global__ void __launch_bounds__(256) k_scoreloss(
        const int* __restrict__ data, const int* __restrict__ cell_nbr,
        const int* __restrict__ drug_nbr, float* __restrict__ out, int loss_idx) {
    int blk = blockIdx.x;
    int tid = threadIdx.x;
    if (blk < 16) {
        int bidx = blk * 256 + tid;
        int c  = data[3 * bidx];
        int d1 = data[3 * bidx + 1];
        int d2 = data[3 * bidx + 2];
        const float4* e1 = (const float4*)(g_emb + (CELL_N + d1) * 64);
        const float4* e2 = (const float4*)(g_emb + (CELL_N + d2) * 64);
        const float4* u  = (const float4*)(g_U + c * 128);
        float s = 0.f;
        #pragma unroll
        for (int t = 0; t < 16; t++) {
            float4 a = e1[t], bb = e2[t], u0 = u[t], u1 = u[16 + t];
            s += a.x * u0.x + a.y * u0.y + a.z * u0.z + a.w * u0.w;
            s += bb.x * u1.x + bb.y * u1.y + bb.z * u1.z + bb.w * u1.w;
            s -= a.x * bb.x + a.y * bb.y + a.z * bb.z + a.w * bb.w;
        }
        out[bidx] = s;
        return;
    }
    __shared__ float nsq[TOT_N];
    __shared__ float red[256];
    for (int i = tid; i < TOT_N; i += 256) nsq[i] = g_normsq[i];
    __syncthreads();
    float ir = 0.f;
    for (int bidx = tid; bidx < BATCH; bidx += 256) {
        int c  = data[3 * bidx];
        int d1 = data[3 * bidx + 1];
        int d2 = data[3 * bidx + 2];
        ir += nsq[c] + nsq[CELL_N + d1] + nsq[CELL_N + d2];
    }
    float nr = 0.f;
    for (int e = tid; e < 1536; e += 256) {
        int set = e >> 8, off = e & 255;
        int hop = set / 3, which = set - hop * 3;
        int nodeidx = data[hop * 3 + which];
        int p = (which == 0) ? cell_nbr[nodeidx * 256 + off] : drug_nbr[nodeidx * 256 + off];
        nr += g_tablesq[p];
    }
    red[tid] = 0.5f * ir + 0.5f * nr;
    __syncthreads();
    #pragma unroll
    for (int off = 128; off; off >>= 1) {
        if (tid < off) red[tid] += red[tid + off];
        __syncthreads();
    }
    if (tid == 0) out[loss_idx] = 1e-6f * red[0] / (float)BATCH;
}

// ---------------- launch ----------------
extern "C" void kernel_launch(void* const* d_in, const int* in_sizes, int n_in,
                              void* d_out, int out_size) {
    const int*   data     = (const int*)  d_in[0];
    const int*   cell_nbr = (const int*)  d_in[1];
    const int*   drug_nbr = (const int*)  d_in[2];
    const float* table    = (const float*)d_in[3];
    const float* cell_pre = (const float*)d_in[4];
    const float* drug_pre = (const float*)d_in[5];
    const float* c1w      = (const float*)d_in[6];
    const float* c1b      = (const float*)d_in[7];
    const float* c2w      = (const float*)d_in[8];
    const float* c2b      = (const float*)d_in[9];
    const float* ow       = (const float*)d_in[10];
    const float* ob       = (const float*)d_in[11];
    const float* aw       = (const float*)d_in[12];
    const float* ab       = (const float*)d_in[13];
    const float* cw       = (const float*)d_in[14];
    float* out = (float*)d_out;

    int ia_smem = (2 * IA_ROWS + 64 + 256 + 128 + 16 + 256) * 4;
    cudaFuncSetAttribute(k_interagg, cudaFuncAttributeMaxDynamicSharedMemorySize, ia_smem);

    k_conv1<<<TSQ_N + TOT_N * 2, 256>>>(cell_pre, drug_pre, c1w, c1b, table);
    k_conv2<<<TOT_N * 2, 256>>>(c2w, c2b);

    dim3 fcg(27, KSPLIT);
    k_fc<<<fcg, 256>>>(ow);
    k_fcred<<<(TOT_N * 16 + 255) / 256, 256>>>(ob);
    k_stats<<<2, 1024>>>();

    k_interagg<<<TOT_N, 256, ia_smem>>>(cell_nbr, drug_nbr, table, aw, ab, cw);
    k_scoreloss<<<17, 256>>>(data, cell_nbr, drug_nbr, out, out_size - 1);
}

// round 14
// speedup vs baseline: 1.2678x; 1.0779x over previous
#include <cuda_runtime.h>

#define CELL_N 76
#define DRUG_N 764
#define TOT_N  840
#define BATCH  4096
#define NPROT  15970
#define KSPLIT 16
#define KCHUNK 512   // 8192 / KSPLIT
#define TSQ_N  ((NPROT + 7) / 8)   // 1997 tablesq blocks

// ---------------- scratch (device globals; no allocs allowed) ----------------
__device__ float g_pool1[TOT_N * 4 * 64 * 64];
__device__ float g_pool2[TOT_N * 8 * 32 * 32];
__device__ float g_fcp  [KSPLIT * TOT_N * 64];
__device__ float g_item [TOT_N * 64];
__device__ float g_stat [4 * 64];          // [mean_c, inv_c, mean_d, inv_d]
__device__ float g_emb  [TOT_N * 64];
__device__ float g_normsq[TOT_N];
__device__ float g_U    [CELL_N * 128];
__device__ float g_tablesq[NPROT];

// ---------------- tablesq (blocks first) + conv1 (merged cell+drug) ----------------
// conv1 compute: fixed-oc pair-blocking, weights loaded once (R13 proven).
#define C1_STR 132
__global__ void __launch_bounds__(256, 4) k_conv1(
        const float* __restrict__ cell_pre, const float* __restrict__ drug_pre,
        const float* __restrict__ w, const float* __restrict__ b,
        const float* __restrict__ table) {
    int blk = blockIdx.x;
    int tid = threadIdx.x;
    if (blk < TSQ_N) {
        int warp = blk * 8 + (tid >> 5);
        int lane = tid & 31;
        if (warp >= NPROT) return;
        const float* r = table + warp * 64;
        float a = r[lane], bb = r[lane + 32];
        float s = a * a + bb * bb;
        #pragma unroll
        for (int o = 16; o; o >>= 1) s += __shfl_down_sync(0xffffffffu, s, o);
        if (lane == 0) g_tablesq[warp] = s;
        return;
    }
    int cblk = blk - TSQ_N;
    int half = cblk & 1;
    int gn;
    const float* x;
    if (cblk < 2 * CELL_N) { gn = cblk >> 1; x = cell_pre + gn * 16384; }
    else { int n = (cblk - 2 * CELL_N) >> 1; gn = CELL_N + n; x = drug_pre + n * 16384; }
    __shared__ float tile[66 * C1_STR];
    __shared__ float ws1[36];
    __shared__ float bs1[4];
    if (tid < 36) ws1[tid] = w[tid];
    if (tid < 4)  bs1[tid] = b[tid];
    int row0 = half * 64 - 1;
    for (int idx = tid; idx < 66 * C1_STR; idx += 256) {
        int r = idx / C1_STR, c = idx - r * C1_STR;
        int y = row0 + r, xx = c - 1;
        tile[idx] = ((unsigned)y < 128u && (unsigned)xx < 128u) ? x[y * 128 + xx] : 0.f;
    }
    __syncthreads();
    int oc = tid >> 6, t64 = tid & 63;
    float wr[9];
    #pragma unroll
    for (int t = 0; t < 9; t++) wr[t] = ws1[oc * 9 + t];
    float bv = bs1[oc];
    #pragma unroll
    for (int i = 0; i < 16; i++) {
        int pos = t64 + i * 64;
        int oy = pos >> 5, oxp = pos & 31;
        float pt[4][6];
        #pragma unroll
        for (int rr = 0; rr < 4; rr++) {
            const float* base = &tile[(2 * oy + rr) * C1_STR + 4 * oxp];
            float4 a = *(const float4*)base;
            float2 b2 = *(const float2*)(base + 4);
            pt[rr][0] = a.x; pt[rr][1] = a.y; pt[rr][2] = a.z;
            pt[rr][3] = a.w; pt[rr][4] = b2.x; pt[rr][5] = b2.y;
        }
        float q[8];
        #pragma unroll
        for (int k = 0; k < 8; k++) q[k] = bv;
        #pragma unroll
        for (int dy = 0; dy < 3; dy++)
        #pragma unroll
        for (int dx = 0; dx < 3; dx++) {
            float wv = wr[dy * 3 + dx];
            q[0] += pt[dy    ][dx    ] * wv;
            q[1] += pt[dy    ][dx + 1] * wv;
            q[2] += pt[dy + 1][dx    ] * wv;
            q[3] += pt[dy + 1][dx + 1] * wv;
            q[4] += pt[dy    ][dx + 2] * wv;
            q[5] += pt[dy    ][dx + 3] * wv;
            q[6] += pt[dy + 1][dx + 2] * wv;
            q[7] += pt[dy + 1][dx + 3] * wv;
        }
        float m0 = fmaxf(fmaxf(q[0], q[1]), fmaxf(q[2], q[3]));
        float m1 = fmaxf(fmaxf(q[4], q[5]), fmaxf(q[6], q[7]));
        float2 v = make_float2(fmaxf(m0, 0.f), fmaxf(m1, 0.f));
        *(float2*)&g_pool1[((gn * 4 + oc) * 64 + half * 32 + oy) * 64 + 2 * oxp] = v;
    }
}

// ---------------- conv2 (4->8) + relu + pool, ichunk-2 weight hoist ----------------
// Weight window loaded per (ichunk, c) = 144 LDS/thread (was 288).
#define C2_STR 68
#define C2_CH  (34 * C2_STR)
__global__ void __launch_bounds__(256, 4) k_conv2(
        const float* __restrict__ w, const float* __restrict__ b) {
    int n = blockIdx.x >> 1, half = blockIdx.x & 1;
    __shared__ float tile[4 * C2_CH];
    __shared__ float ws[288];
    int tid = threadIdx.x;
    int row0 = half * 32 - 1;
    for (int i = tid; i < 288; i += 256) ws[i] = w[i];
    for (int idx = tid; idx < 4 * 34 * 66; idx += 256) {
        int c = idx / (34 * 66), rem = idx - c * (34 * 66);
        int r = rem / 66, cc = rem - r * 66;
        int y = row0 + r, xx = cc - 1;
        tile[c * C2_CH + r * C2_STR + cc] =
            ((unsigned)y < 64u && (unsigned)xx < 64u)
          ? g_pool1[((n * 4 + c) * 64 + y) * 64 + xx] : 0.f;
    }
    __syncthreads();
    int oc = tid >> 5, lane = tid & 31;
    float bs = b[oc];
    #pragma unroll
    for (int ic = 0; ic < 4; ic++) {
        float q[2][8];
        #pragma unroll
        for (int i2 = 0; i2 < 2; i2++)
            #pragma unroll
            for (int k = 0; k < 8; k++) q[i2][k] = bs;
        #pragma unroll
        for (int c = 0; c < 4; c++) {
            float wr[9];
            #pragma unroll
            for (int t = 0; t < 9; t++) wr[t] = ws[oc * 36 + c * 9 + t];
            #pragma unroll
            for (int i2 = 0; i2 < 2; i2++) {
                int pos = lane + (ic * 2 + i2) * 32;
                int oy = pos >> 4, oxp = pos & 15;
                float pt[4][6];
                #pragma unroll
                for (int rr = 0; rr < 4; rr++) {
                    const float* base = &tile[c * C2_CH + (2 * oy + rr) * C2_STR + 4 * oxp];
                    float4 a = *(const float4*)base;
                    float2 b2 = *(const float2*)(base + 4);
                    pt[rr][0] = a.x; pt[rr][1] = a.y; pt[rr][2] = a.z;
                    pt[rr][3] = a.w; pt[rr][4] = b2.x; pt[rr][5] = b2.y;
                }
                #pragma unroll
                for (int dy = 0; dy < 3; dy++)
                #pragma unroll
                for (int dx = 0; dx < 3; dx++) {
                    float wv = wr[dy * 3 + dx];
                    q[i2][0] += pt[dy    ][dx    ] * wv;
                    q[i2][1] += pt[dy    ][dx + 1] * wv;
                    q[i2][2] += pt[dy + 1][dx    ] * wv;
                    q[i2][3] += pt[dy + 1][dx + 1] * wv;
                    q[i2][4] += pt[dy    ][dx + 2] * wv;
                    q[i2][5] += pt[dy    ][dx + 3] * wv;
                    q[i2][6] += pt[dy + 1][dx + 2] * wv;
                    q[i2][7] += pt[dy + 1][dx + 3] * wv;
                }
            }
        }
        #pragma unroll
        for (int i2 = 0; i2 < 2; i2++) {
            int pos = lane + (ic * 2 + i2) * 32;
            int oy = pos >> 4, oxp = pos & 15;
            float m0 = fmaxf(fmaxf(q[i2][0], q[i2][1]), fmaxf(q[i2][2], q[i2][3]));
            float m1 = fmaxf(fmaxf(q[i2][4], q[i2][5]), fmaxf(q[i2][6], q[i2][7]));
            float2 v = make_float2(fmaxf(m0, 0.f), fmaxf(m1, 0.f));
            *(float2*)&g_pool2[((n * 8 + oc) * 32 + half * 16 + oy) * 32 + 2 * oxp] = v;
        }
    }
}

// ---------------- FC as tiled GEMM with K-split ----------------
__global__ void __launch_bounds__(256) k_fc(const float* __restrict__ W) {
    int m0 = blockIdx.x * 32;
    int kb = blockIdx.y;
    int k0 = kb * KCHUNK;
    __shared__ float Xs[32][64];
    __shared__ float Ws[64][68];
    int tid = threadIdx.x;
    int tm = tid >> 5, tn = tid & 31;
    float acc[4][2] = {};
    for (int kt = 0; kt < KCHUNK; kt += 64) {
        #pragma unroll
        for (int i = 0; i < 8; i++) {
            int idx = tid + i * 256;
            int r = idx >> 6, c = idx & 63;
            int m = m0 + r;
            Xs[r][c] = (m < TOT_N) ? g_pool2[m * 8192 + k0 + kt + c] : 0.f;
        }
        #pragma unroll
        for (int i = 0; i < 16; i++) {
            int idx = tid + i * 256;
            int j = idx >> 6, c = idx & 63;
            Ws[j][c] = W[j * 8192 + k0 + kt + c];
        }
        __syncthreads();
        #pragma unroll
        for (int kk = 0; kk < 64; kk += 4) {
            float4 w0 = *(const float4*)&Ws[tn     ][kk];
            float4 w1 = *(const float4*)&Ws[tn + 32][kk];
            #pragma unroll
            for (int r = 0; r < 4; r++) {
                float4 xv = *(const float4*)&Xs[tm * 4 + r][kk];
                acc[r][0] += xv.x * w0.x + xv.y * w0.y + xv.z * w0.z + xv.w * w0.w;
                acc[r][1] += xv.x * w1.x + xv.y * w1.y + xv.z * w1.z + xv.w * w1.w;
            }
        }
        __syncthreads();
    }
    #pragma unroll
    for (int r = 0; r < 4; r++) {
        int m = m0 + tm * 4 + r;
        if (m < TOT_N) {
            g_fcp[(kb * TOT_N + m) * 64 + tn     ] = acc[r][0];
            g_fcp[(kb * TOT_N + m) * 64 + tn + 32] = acc[r][1];
        }
    }
}

// ---------------- reduce K-split partials + bias -> g_item (float4) ----------------
__global__ void k_fcred(const float* __restrict__ b) {
    int v = blockIdx.x * blockDim.x + threadIdx.x;     // float4 index
    if (v >= TOT_N * 16) return;
    int j4 = (v & 15) * 4;
    float4 s = *(const float4*)&b[j4];
    #pragma unroll
    for (int kb = 0; kb < KSPLIT; kb++) {
        float4 p = *(const float4*)&g_fcp[kb * TOT_N * 64 + v * 4];
        s.x += p.x; s.y += p.y; s.z += p.z; s.w += p.w;
    }
    *(float4*)&g_item[v * 4] = s;
}

// ---------------- stats only: mean + rsqrt(var) per feature per group ----------------
template<int ROW0, int N, int SBASE>
__device__ __forceinline__ void stats_body(float2* red) {
    int tid = threadIdx.x;
    int j = tid & 63, q = tid >> 6;
    constexpr int R = (N + 15) / 16;
    float s = 0.f, ss = 0.f;
    #pragma unroll
    for (int i = 0; i < R; i++) {
        int n = q + i * 16;
        if (n < N) {
            float v = g_item[(ROW0 + n) * 64 + j];
            s += v;
            ss += v * v;
        }
    }
    red[tid] = make_float2(s, ss);
    __syncthreads();
    if (tid < 64) {
        float S = 0.f, SS = 0.f;
        #pragma unroll
        for (int k = 0; k < 16; k++) {
            float2 r = red[tid + 64 * k];
            S += r.x; SS += r.y;
        }
        float m = S / (float)N;
        float var = (SS - (float)N * m * m) / (float)(N - 1);
        g_stat[SBASE + tid] = m;
        g_stat[SBASE + 64 + tid] = rsqrtf(var);
    }
}

__global__ void __launch_bounds__(1024) k_stats() {
    __shared__ float2 red[1024];
    if (blockIdx.x == 0) stats_body<0, CELL_N, 0>(red);
    else                 stats_body<CELL_N, DRUG_N, 128>(red);
}

// ---------------- interact + agg fused (normalize query on the fly) ----------------
#define IA_ROWS (128 * 65)
__global__ void __launch_bounds__(256) k_interagg(
        const int* __restrict__ cell_nbr, const int* __restrict__ drug_nbr,
        const float* __restrict__ table,
        const float* __restrict__ W, const float* __restrict__ b,
        const float* __restrict__ combw) {
    int n = blockIdx.x;
    const int* nbr;
    int sbase;
    if (n < CELL_N) { nbr = cell_nbr + n * 256; sbase = 0; }
    else { nbr = drug_nbr + (n - CELL_N) * 256; sbase = 128; }

    extern __shared__ float sm[];
    float* rows = sm;                      // 2 * IA_ROWS
    float* it   = sm + 2 * IA_ROWS;        // 64
    float* sc   = it + 64;                 // 256
    float* xr   = sc + 256;                // 128
    float* wred = xr + 128;                // 16
    float* part = wred + 16;               // 256
    __shared__ int idxs[256];

    int tid = threadIdx.x;
    int warp = tid >> 5, lane = tid & 31;
    int hop = tid >> 7, wg = tid & 127;
    idxs[tid] = nbr[tid];
    if (tid < 64)
        it[tid] = (g_item[n * 64 + tid] - g_stat[sbase + tid]) * g_stat[sbase + 64 + tid];
    __syncthreads();
    const float4* t4 = (const float4*)table;
    for (int e = tid; e < 2 * 128 * 16; e += 256) {
        int hk = e >> 4, q = e & 15;
        int h = hk >> 7, k = hk & 127;
        float4 v = t4[idxs[h * 128 + k] * 16 + q];
        float* dst = &rows[h * IA_ROWS + k * 65 + q * 4];
        dst[0] = v.x; dst[1] = v.y; dst[2] = v.z; dst[3] = v.w;
    }
    __syncthreads();
    const float* myrow = &rows[hop * IA_ROWS + wg * 65];
    float s = 0.f;
    #pragma unroll 8
    for (int d = 0; d < 64; d++) s += myrow[d] * it[d];
    float m = s;
    #pragma unroll
    for (int o = 16; o; o >>= 1) m = fmaxf(m, __shfl_xor_sync(0xffffffffu, m, o));
    if (lane == 0) wred[warp] = m;
    __syncthreads();
    int wb = (hop << 2);
    float mx = fmaxf(fmaxf(wred[wb], wred[wb + 1]), fmaxf(wred[wb + 2], wred[wb + 3]));
    float e = expf(s - mx);
    sc[tid] = e;
    float t = e;
    #pragma unroll
    for (int o = 16; o; o >>= 1) t += __shfl_xor_sync(0xffffffffu, t, o);
    if (lane == 0) wred[8 + warp] = t;
    __syncthreads();
    float inv = 1.f / (wred[8 + wb] + wred[9 + wb] + wred[10 + wb] + wred[11 + wb]);
    int d = wg & 63, kh = wg >> 6;
    const float* rb = &rows[hop * IA_ROWS + (kh * 64) * 65];
    const float* sb = &sc[hop * 128 + kh * 64];
    float o = 0.f;
    #pragma unroll 8
    for (int k2 = 0; k2 < 64; k2++) o += sb[k2] * rb[k2 * 65 + d];
    part[tid] = o;
    __syncthreads();
    if (wg < 64) {
        int base = hop << 7;
        xr[hop * 64 + wg] = (part[base + wg] + part[base + 64 + wg]) * inv;
    }
    __syncthreads();
    int j = tid & 63, sl = tid >> 6;
    float ag = 0.f;
    const float* wrow = &W[j * 128 + sl * 32];
    const float* xs = &xr[sl * 32];
    #pragma unroll 8
    for (int t2 = 0; t2 < 32; t2++) ag += wrow[t2] * xs[t2];
    part[tid] = ag;
    __syncthreads();
    if (tid < 64) {
        float v = part[tid] + part[tid + 64] + part[tid + 128] + part[tid + 192] + b[tid];
        g_emb[n * 64 + tid] = v;
        it[tid] = v;
        sc[tid] = v * v;
    }
    __syncthreads();
    if (tid < 32) {
        float v = sc[tid] + sc[tid + 32];
        #pragma unroll
        for (int o2 = 16; o2; o2 >>= 1) v += __shfl_down_sync(0xffffffffu, v, o2);
        if (tid == 0) g_normsq[n] = v;
    }
    if (n < CELL_N && tid < 128) {
        float s2 = 0.f;
        #pragma unroll 8
        for (int j2 = 0; j2 < 64; j2++) s2 += combw[j2 * 128 + tid] * it[j2];
        g_U[n * 128 + tid] = s2;
    }
}

// ---------------- score (blocks 0..15, float4) + loss (block 16) ----------------
__global__ void __launch_bounds__(256) k_scoreloss(
        const int* __restrict__ data, const int* __restrict__ cell_nbr,
        const int* __restrict__ drug_nbr, float* __restrict__ out, int loss_idx) {
    int blk = blockIdx.x;
    int tid = threadIdx.x;
    if (blk < 16) {
        int bidx = blk * 256 + tid;
        int c  = data[3 * bidx];
        int d1 = data[3 * bidx + 1];
        int d2 = data[3 * bidx + 2];
        const float4* e1 = (const float4*)(g_emb + (CELL_N + d1) * 64);
        const float4* e2 = (const float4*)(g_emb + (CELL_N + d2) * 64);
        const float4* u  = (const float4*)(g_U + c * 128);
        float s = 0.f;
        #pragma unroll
        for (int t = 0; t < 16; t++) {
            float4 a = e1[t], bb = e2[t], u0 = u[t], u1 = u[16 + t];
            s += a.x * u0.x + a.y * u0.y + a.z * u0.z + a.w * u0.w;
            s += bb.x * u1.x + bb.y * u1.y + bb.z * u1.z + bb.w * u1.w;
            s -= a.x * bb.x + a.y * bb.y + a.z * bb.z + a.w * bb.w;
        }
        out[bidx] = s;
        return;
    }
    __shared__ float nsq[TOT_N];
    __shared__ float red[256];
    for (int i = tid; i < TOT_N; i += 256) nsq[i] = g_normsq[i];
    __syncthreads();
    float ir = 0.f;
    for (int bidx = tid; bidx < BATCH; bidx += 256) {
        int c  = data[3 * bidx];
        int d1 = data[3 * bidx + 1];
        int d2 = data[3 * bidx + 2];
        ir += nsq[c] + nsq[CELL_N + d1] + nsq[CELL_N + d2];
    }
    float nr = 0.f;
    for (int e = tid; e < 1536; e += 256) {
        int set = e >> 8, off = e & 255;
        int hop = set / 3, which = set - hop * 3;
        int nodeidx = data[hop * 3 + which];
        int p = (which == 0) ? cell_nbr[nodeidx * 256 + off] : drug_nbr[nodeidx * 256 + off];
        nr += g_tablesq[p];
    }
    red[tid] = 0.5f * ir + 0.5f * nr;
    __syncthreads();
    #pragma unroll
    for (int off = 128; off; off >>= 1) {
        if (tid < off) red[tid] += red[tid + off];
        __syncthreads();
    }
    if (tid == 0) out[loss_idx] = 1e-6f * red[0] / (float)BATCH;
}

// ---------------- launch ----------------
extern "C" void kernel_launch(void* const* d_in, const int* in_sizes, int n_in,
                              void* d_out, int out_size) {
    const int*   data     = (const int*)  d_in[0];
    const int*   cell_nbr = (const int*)  d_in[1];
    const int*   drug_nbr = (const int*)  d_in[2];
    const float* table    = (const float*)d_in[3];
    const float* cell_pre = (const float*)d_in[4];
    const float* drug_pre = (const float*)d_in[5];
    const float* c1w      = (const float*)d_in[6];
    const float* c1b      = (const float*)d_in[7];
    const float* c2w      = (const float*)d_in[8];
    const float* c2b      = (const float*)d_in[9];
    const float* ow       = (const float*)d_in[10];
    const float* ob       = (const float*)d_in[11];
    const float* aw       = (const float*)d_in[12];
    const float* ab       = (const float*)d_in[13];
    const float* cw       = (const float*)d_in[14];
    float* out = (float*)d_out;

    int ia_smem = (2 * IA_ROWS + 64 + 256 + 128 + 16 + 256) * 4;
    cudaFuncSetAttribute(k_interagg, cudaFuncAttributeMaxDynamicSharedMemorySize, ia_smem);

    k_conv1<<<TSQ_N + TOT_N * 2, 256>>>(cell_pre, drug_pre, c1w, c1b, table);
    k_conv2<<<TOT_N * 2, 256>>>(c2w, c2b);

    dim3 fcg(27, KSPLIT);
    k_fc<<<fcg, 256>>>(ow);
    k_fcred<<<(TOT_N * 16 + 255) / 256, 256>>>(ob);
    k_stats<<<2, 1024>>>();

    k_interagg<<<TOT_N, 256, ia_smem>>>(cell_nbr, drug_nbr, table, aw, ab, cw);
    k_scoreloss<<<17, 256>>>(data, cell_nbr, drug_nbr, out, out_size - 1);
}

// round 15
// speedup vs baseline: 1.2773x; 1.0075x over previous
#include <cuda_runtime.h>

#define CELL_N 76
#define DRUG_N 764
#define TOT_N  840
#define BATCH  4096
#define NPROT  15970
#define KSPLIT 16
#define KCHUNK 512   // 8192 / KSPLIT
#define TSQ_N  ((NPROT + 7) / 8)   // 1997 tablesq blocks
#define FCR_BLOCKS 53              // ceil(840*16 / 256)

// ---------------- scratch (device globals; no allocs allowed) ----------------
__device__ float g_pool1[TOT_N * 4 * 64 * 64];
__device__ float g_pool2[TOT_N * 8 * 32 * 32];
__device__ float g_fcp  [KSPLIT * TOT_N * 64];
__device__ float g_item [TOT_N * 64];
__device__ float g_stat [4 * 64];          // [mean_c, inv_c, mean_d, inv_d]
__device__ float4 g_sp[2 * FCR_BLOCKS * 16];   // per-(group, block, q4) item sums
__device__ float4 g_sq[2 * FCR_BLOCKS * 16];   // per-(group, block, q4) item sumsq
__device__ float g_emb  [TOT_N * 64];
__device__ float g_normsq[TOT_N];
__device__ float g_U    [CELL_N * 128];
__device__ float g_tablesq[NPROT];

// ---------------- tablesq (blocks first) + conv1 (merged cell+drug) ----------------
// conv1 compute: fixed-oc pair-blocking, weights loaded once (R13 proven).
#define C1_STR 132
__global__ void __launch_bounds__(256, 5) k_conv1(
        const float* __restrict__ cell_pre, const float* __restrict__ drug_pre,
        const float* __restrict__ w, const float* __restrict__ b,
        const float* __restrict__ table) {
    int blk = blockIdx.x;
    int tid = threadIdx.x;
    if (blk < TSQ_N) {
        int warp = blk * 8 + (tid >> 5);
        int lane = tid & 31;
        if (warp >= NPROT) return;
        const float* r = table + warp * 64;
        float a = r[lane], bb = r[lane + 32];
        float s = a * a + bb * bb;
        #pragma unroll
        for (int o = 16; o; o >>= 1) s += __shfl_down_sync(0xffffffffu, s, o);
        if (lane == 0) g_tablesq[warp] = s;
        return;
    }
    int cblk = blk - TSQ_N;
    int half = cblk & 1;
    int gn;
    const float* x;
    if (cblk < 2 * CELL_N) { gn = cblk >> 1; x = cell_pre + gn * 16384; }
    else { int n = (cblk - 2 * CELL_N) >> 1; gn = CELL_N + n; x = drug_pre + n * 16384; }
    __shared__ float tile[66 * C1_STR];
    __shared__ float ws1[36];
    __shared__ float bs1[4];
    if (tid < 36) ws1[tid] = w[tid];
    if (tid < 4)  bs1[tid] = b[tid];
    int row0 = half * 64 - 1;
    for (int idx = tid; idx < 66 * C1_STR; idx += 256) {
        int r = idx / C1_STR, c = idx - r * C1_STR;
        int y = row0 + r, xx = c - 1;
        tile[idx] = ((unsigned)y < 128u && (unsigned)xx < 128u) ? x[y * 128 + xx] : 0.f;
    }
    __syncthreads();
    int oc = tid >> 6, t64 = tid & 63;
    float wr[9];
    #pragma unroll
    for (int t = 0; t < 9; t++) wr[t] = ws1[oc * 9 + t];
    float bv = bs1[oc];
    #pragma unroll
    for (int i = 0; i < 16; i++) {
        int pos = t64 + i * 64;
        int oy = pos >> 5, oxp = pos & 31;
        float pt[4][6];
        #pragma unroll
        for (int rr = 0; rr < 4; rr++) {
            const float* base = &tile[(2 * oy + rr) * C1_STR + 4 * oxp];
            float4 a = *(const float4*)base;
            float2 b2 = *(const float2*)(base + 4);
            pt[rr][0] = a.x; pt[rr][1] = a.y; pt[rr][2] = a.z;
            pt[rr][3] = a.w; pt[rr][4] = b2.x; pt[rr][5] = b2.y;
        }
        float q[8];
        #pragma unroll
        for (int k = 0; k < 8; k++) q[k] = bv;
        #pragma unroll
        for (int dy = 0; dy < 3; dy++)
        #pragma unroll
        for (int dx = 0; dx < 3; dx++) {
            float wv = wr[dy * 3 + dx];
            q[0] += pt[dy    ][dx    ] * wv;
            q[1] += pt[dy    ][dx + 1] * wv;
            q[2] += pt[dy + 1][dx    ] * wv;
            q[3] += pt[dy + 1][dx + 1] * wv;
            q[4] += pt[dy    ][dx + 2] * wv;
            q[5] += pt[dy    ][dx + 3] * wv;
            q[6] += pt[dy + 1][dx + 2] * wv;
            q[7] += pt[dy + 1][dx + 3] * wv;
        }
        float m0 = fmaxf(fmaxf(q[0], q[1]), fmaxf(q[2], q[3]));
        float m1 = fmaxf(fmaxf(q[4], q[5]), fmaxf(q[6], q[7]));
        float2 v = make_float2(fmaxf(m0, 0.f), fmaxf(m1, 0.f));
        *(float2*)&g_pool1[((gn * 4 + oc) * 64 + half * 32 + oy) * 64 + 2 * oxp] = v;
    }
}

// ---------------- conv2 (4->8) + relu + pool, ichunk-2 weight hoist (R14 proven) ----------------
#define C2_STR 68
#define C2_CH  (34 * C2_STR)
__global__ void __launch_bounds__(256, 4) k_conv2(
        const float* __restrict__ w, const float* __restrict__ b) {
    int n = blockIdx.x >> 1, half = blockIdx.x & 1;
    __shared__ float tile[4 * C2_CH];
    __shared__ float ws[288];
    int tid = threadIdx.x;
    int row0 = half * 32 - 1;
    for (int i = tid; i < 288; i += 256) ws[i] = w[i];
    for (int idx = tid; idx < 4 * 34 * 66; idx += 256) {
        int c = idx / (34 * 66), rem = idx - c * (34 * 66);
        int r = rem / 66, cc = rem - r * 66;
        int y = row0 + r, xx = cc - 1;
        tile[c * C2_CH + r * C2_STR + cc] =
            ((unsigned)y < 64u && (unsigned)xx < 64u)
          ? g_pool1[((n * 4 + c) * 64 + y) * 64 + xx] : 0.f;
    }
    __syncthreads();
    int oc = tid >> 5, lane = tid & 31;
    float bs = b[oc];
    #pragma unroll
    for (int ic = 0; ic < 4; ic++) {
        float q[2][8];
        #pragma unroll
        for (int i2 = 0; i2 < 2; i2++)
            #pragma unroll
            for (int k = 0; k < 8; k++) q[i2][k] = bs;
        #pragma unroll
        for (int c = 0; c < 4; c++) {
            float wr[9];
            #pragma unroll
            for (int t = 0; t < 9; t++) wr[t] = ws[oc * 36 + c * 9 + t];
            #pragma unroll
            for (int i2 = 0; i2 < 2; i2++) {
                int pos = lane + (ic * 2 + i2) * 32;
                int oy = pos >> 4, oxp = pos & 15;
                float pt[4][6];
                #pragma unroll
                for (int rr = 0; rr < 4; rr++) {
                    const float* base = &tile[c * C2_CH + (2 * oy + rr) * C2_STR + 4 * oxp];
                    float4 a = *(const float4*)base;
                    float2 b2 = *(const float2*)(base + 4);
                    pt[rr][0] = a.x; pt[rr][1] = a.y; pt[rr][2] = a.z;
                    pt[rr][3] = a.w; pt[rr][4] = b2.x; pt[rr][5] = b2.y;
                }
                #pragma unroll
                for (int dy = 0; dy < 3; dy++)
                #pragma unroll
                for (int dx = 0; dx < 3; dx++) {
                    float wv = wr[dy * 3 + dx];
                    q[i2][0] += pt[dy    ][dx    ] * wv;
                    q[i2][1] += pt[dy    ][dx + 1] * wv;
                    q[i2][2] += pt[dy + 1][dx    ] * wv;
                    q[i2][3] += pt[dy + 1][dx + 1] * wv;
                    q[i2][4] += pt[dy    ][dx + 2] * wv;
                    q[i2][5] += pt[dy    ][dx + 3] * wv;
                    q[i2][6] += pt[dy + 1][dx + 2] * wv;
                    q[i2][7] += pt[dy + 1][dx + 3] * wv;
                }
            }
        }
        #pragma unroll
        for (int i2 = 0; i2 < 2; i2++) {
            int pos = lane + (ic * 2 + i2) * 32;
            int oy = pos >> 4, oxp = pos & 15;
            float m0 = fmaxf(fmaxf(q[i2][0], q[i2][1]), fmaxf(q[i2][2], q[i2][3]));
            float m1 = fmaxf(fmaxf(q[i2][4], q[i2][5]), fmaxf(q[i2][6], q[i2][7]));
            float2 v = make_float2(fmaxf(m0, 0.f), fmaxf(m1, 0.f));
            *(float2*)&g_pool2[((n * 8 + oc) * 32 + half * 16 + oy) * 32 + 2 * oxp] = v;
        }
    }
}

// ---------------- FC as tiled GEMM with K-split (float4 global loads) ----------------
__global__ void __launch_bounds__(256) k_fc(const float* __restrict__ W) {
    int m0 = blockIdx.x * 32;
    int kb = blockIdx.y;
    int k0 = kb * KCHUNK;
    __shared__ float Xs[32][64];
    __shared__ float Ws[64][68];
    int tid = threadIdx.x;
    int tm = tid >> 5, tn = tid & 31;
    const float4* P4 = (const float4*)g_pool2;
    const float4* W4 = (const float4*)W;
    float acc[4][2] = {};
    for (int kt = 0; kt < KCHUNK; kt += 64) {
        int kbase4 = (k0 + kt) >> 2;                  // float4 offset within row
        #pragma unroll
        for (int i = 0; i < 2; i++) {
            int idx = tid + i * 256;                  // 0..511
            int r = idx >> 4, f = idx & 15;
            int m = m0 + r;
            float4 v = (m < TOT_N) ? P4[m * 2048 + kbase4 + f]
                                   : make_float4(0.f, 0.f, 0.f, 0.f);
            *(float4*)&Xs[r][f * 4] = v;
        }
        #pragma unroll
        for (int i = 0; i < 4; i++) {
            int idx = tid + i * 256;                  // 0..1023
            int j = idx >> 4, f = idx & 15;
            *(float4*)&Ws[j][f * 4] = W4[j * 2048 + kbase4 + f];
        }
        __syncthreads();
        #pragma unroll
        for (int kk = 0; kk < 64; kk += 4) {
            float4 w0 = *(const float4*)&Ws[tn     ][kk];
            float4 w1 = *(const float4*)&Ws[tn + 32][kk];
            #pragma unroll
            for (int r = 0; r < 4; r++) {
                float4 xv = *(const float4*)&Xs[tm * 4 + r][kk];
                acc[r][0] += xv.x * w0.x + xv.y * w0.y + xv.z * w0.z + xv.w * w0.w;
                acc[r][1] += xv.x * w1.x + xv.y * w1.y + xv.z * w1.z + xv.w * w1.w;
            }
        }
        __syncthreads();
    }
    #pragma unroll
    for (int r = 0; r < 4; r++) {
        int m = m0 + tm * 4 + r;
        if (m < TOT_N) {
            g_fcp[(kb * TOT_N + m) * 64 + tn     ] = acc[r][0];
            g_fcp[(kb * TOT_N + m) * 64 + tn + 32] = acc[r][1];
        }
    }
}

// ---------------- fcred: K-split reduce + bias -> g_item, plus stats partials ----------------
// Block covers 16 rows x 64 features. Per-(group, q4) partial sums/sumsq to g_sp/g_sq.
__global__ void __launch_bounds__(256) k_fcred(const float* __restrict__ b) {
    int tid = threadIdx.x, blk = blockIdx.x;
    int v = blk * 256 + tid;                 // float4 index
    bool ok = v < TOT_N * 16;
    int q4 = v & 15;
    float4 s = make_float4(0.f, 0.f, 0.f, 0.f);
    if (ok) {
        s = *(const float4*)&b[q4 * 4];
        #pragma unroll
        for (int kb = 0; kb < KSPLIT; kb++) {
            float4 p = *(const float4*)&g_fcp[kb * TOT_N * 64 + v * 4];
            s.x += p.x; s.y += p.y; s.z += p.z; s.w += p.w;
        }
        *(float4*)&g_item[v * 4] = s;
    }
    __shared__ float4 sm_s[256];
    __shared__ float4 sm_q[256];
    sm_s[tid] = s;
    sm_q[tid] = make_float4(s.x * s.x, s.y * s.y, s.z * s.z, s.w * s.w);
    __syncthreads();
    if (tid < 32) {
        int q = tid & 15, g = tid >> 4;
        float4 S = make_float4(0.f, 0.f, 0.f, 0.f);
        float4 Q = make_float4(0.f, 0.f, 0.f, 0.f);
        #pragma unroll
        for (int r = 0; r < 16; r++) {
            int row = blk * 16 + r;
            int grp = (row < CELL_N) ? 0 : 1;
            if (row < TOT_N && grp == g) {
                float4 a = sm_s[r * 16 + q];
                float4 c = sm_q[r * 16 + q];
                S.x += a.x; S.y += a.y; S.z += a.z; S.w += a.w;
                Q.x += c.x; Q.y += c.y; Q.z += c.z; Q.w += c.w;
            }
        }
        g_sp[(g * FCR_BLOCKS + blk) * 16 + q] = S;
        g_sq[(g * FCR_BLOCKS + blk) * 16 + q] = Q;
    }
}

// ---------------- final stats: reduce partials -> mean, rsqrt(var) ----------------
__global__ void k_stats(int dummy) {
    int tid = threadIdx.x;                  // 128 threads
    int g = tid >> 6, j = tid & 63;
    int q = j >> 2, c = j & 3;
    const float* sp = (const float*)g_sp;
    const float* sq = (const float*)g_sq;
    float S = 0.f, Q = 0.f;
    for (int blk = 0; blk < FCR_BLOCKS; blk++) {
        int idx = ((g * FCR_BLOCKS + blk) * 16 + q) * 4 + c;
        S += sp[idx];
        Q += sq[idx];
    }
    float N = g ? (float)DRUG_N : (float)CELL_N;
    float m = S / N;
    float var = (Q - N * m * m) / (N - 1.f);
    g_stat[g * 128 + j] = m;
    g_stat[g * 128 + 64 + j] = rsqrtf(var);
}

// ---------------- interact + agg fused (normalize query on the fly) ----------------
#define IA_ROWS (128 * 65)
__global__ void __launch_bounds__(256) k_interagg(
        const int* __restrict__ cell_nbr, const int* __restrict__ drug_nbr,
        const float* __restrict__ table,
        const float* __restrict__ W, const float* __restrict__ b,
        const float* __restrict__ combw) {
    int n = blockIdx.x;
    const int* nbr;
    int sbase;
    if (n < CELL_N) { nbr = cell_nbr + n * 256; sbase = 0; }
    else { nbr = drug_nbr + (n - CELL_N) * 256; sbase = 128; }

    extern __shared__ float sm[];
    float* rows = sm;                      // 2 * IA_ROWS
    float* it   = sm + 2 * IA_ROWS;        // 64
    float* sc   = it + 64;                 // 256
    float* xr   = sc + 256;                // 128
    float* wred = xr + 128;                // 16
    float* part = wred + 16;               // 256
    __shared__ int idxs[256];

    int tid = threadIdx.x;
    int warp = tid >> 5, lane = tid & 31;
    int hop = tid >> 7, wg = tid & 127;
    idxs[tid] = nbr[tid];
    if (tid < 64)
        it[tid] = (g_item[n * 64 + tid] - g_stat[sbase + tid]) * g_stat[sbase + 64 + tid];
    __syncthreads();
    const float4* t4 = (const float4*)table;
    for (int e = tid; e < 2 * 128 * 16; e += 256) {
        int hk = e >> 4, q = e & 15;
        int h = hk >> 7, k = hk & 127;
        float4 v = t4[idxs[h * 128 + k] * 16 + q];
        float* dst = &rows[h * IA_ROWS + k * 65 + q * 4];
        dst[0] = v.x; dst[1] = v.y; dst[2] = v.z; dst[3] = v.w;
    }
    __syncthreads();
    const float* myrow = &rows[hop * IA_ROWS + wg * 65];
    float s = 0.f;
    #pragma unroll 8
    for (int d = 0; d < 64; d++) s += myrow[d] * it[d];
    float m = s;
    #pragma unroll
    for (int o = 16; o; o >>= 1) m = fmaxf(m, __shfl_xor_sync(0xffffffffu, m, o));
    if (lane == 0) wred[warp] = m;
    __syncthreads();
    int wb = (hop << 2);
    float mx = fmaxf(fmaxf(wred[wb], wred[wb + 1]), fmaxf(wred[wb + 2], wred[wb + 3]));
    float e = expf(s - mx);
    sc[tid] = e;
    float t = e;
    #pragma unroll
    for (int o = 16; o; o >>= 1) t += __shfl_xor_sync(0xffffffffu, t, o);
    if (lane == 0) wred[8 + warp] = t;
    __syncthreads();
    float inv = 1.f / (wred[8 + wb] + wred[9 + wb] + wred[10 + wb] + wred[11 + wb]);
    int d = wg & 63, kh = wg >> 6;
    const float* rb = &rows[hop * IA_ROWS + (kh * 64) * 65];
    const float* sb = &sc[hop * 128 + kh * 64];
    float o = 0.f;
    #pragma unroll 8
    for (int k2 = 0; k2 < 64; k2++) o += sb[k2] * rb[k2 * 65 + d];
    part[tid] = o;
    __syncthreads();
    if (wg < 64) {
        int base = hop << 7;
        xr[hop * 64 + wg] = (part[base + wg] + part[base + 64 + wg]) * inv;
    }
    __syncthreads();
    int j = tid & 63, sl = tid >> 6;
    float ag = 0.f;
    const float* wrow = &W[j * 128 + sl * 32];
    const float* xs = &xr[sl * 32];
    #pragma unroll 8
    for (int t2 = 0; t2 < 32; t2++) ag += wrow[t2] * xs[t2];
    part[tid] = ag;
    __syncthreads();
    if (tid < 64) {
        float v = part[tid] + part[tid + 64] + part[tid + 128] + part[tid + 192] + b[tid];
        g_emb[n * 64 + tid] = v;
        it[tid] = v;
        sc[tid] = v * v;
    }
    __syncthreads();
    if (tid < 32) {
        float v = sc[tid] + sc[tid + 32];
        #pragma unroll
        for (int o2 = 16; o2; o2 >>= 1) v += __shfl_down_sync(0xffffffffu, v, o2);
        if (tid == 0) g_normsq[n] = v;
    }
    if (n < CELL_N && tid < 128) {
        float s2 = 0.f;
        #pragma unroll 8
        for (int j2 = 0; j2 < 64; j2++) s2 += combw[j2 * 128 + tid] * it[j2];
        g_U[n * 128 + tid] = s2;
    }
}

// ---------------- score (blocks 0..15, float4) + loss (block 16) ----------------
__global__ void __launch_bounds__(256) k_scoreloss(
        const int* __restrict__ data, const int* __restrict__ cell_nbr,
        const int* __restrict__ drug_nbr, float* __restrict__ out, int loss_idx) {
    int blk = blockIdx.x;
    int tid = threadIdx.x;
    if (blk < 16) {
        int bidx = blk * 256 + tid;
        int c  = data[3 * bidx];
        int d1 = data[3 * bidx + 1];
        int d2 = data[3 * bidx + 2];
        const float4* e1 = (const float4*)(g_emb + (CELL_N + d1) * 64);
        const float4* e2 = (const float4*)(g_emb + (CELL_N + d2) * 64);
        const float4* u  = (const float4*)(g_U + c * 128);
        float s = 0.f;
        #pragma unroll
        for (int t = 0; t < 16; t++) {
            float4 a = e1[t], bb = e2[t], u0 = u[t], u1 = u[16 + t];
            s += a.x * u0.x + a.y * u0.y + a.z * u0.z + a.w * u0.w;
            s += bb.x * u1.x + bb.y * u1.y + bb.z * u1.z + bb.w * u1.w;
            s -= a.x * bb.x + a.y * bb.y + a.z * bb.z + a.w * bb.w;
        }
        out[bidx] = s;
        return;
    }
    __shared__ float nsq[TOT_N];
    __shared__ float red[256];
    for (int i = tid; i < TOT_N; i += 256) nsq[i] = g_normsq[i];
    __syncthreads();
    float ir = 0.f;
    for (int bidx = tid; bidx < BATCH; bidx += 256) {
        int c  = data[3 * bidx];
        int d1 = data[3 * bidx + 1];
        int d2 = data[3 * bidx + 2];
        ir += nsq[c] + nsq[CELL_N + d1] + nsq[CELL_N + d2];
    }
    float nr = 0.f;
    for (int e = tid; e < 1536; e += 256) {
        int set = e >> 8, off = e & 255;
        int hop = set / 3, which = set - hop * 3;
        int nodeidx = data[hop * 3 + which];
        int p = (which == 0) ? cell_nbr[nodeidx * 256 + off] : drug_nbr[nodeidx * 256 + off];
        nr += g_tablesq[p];
    }
    red[tid] = 0.5f * ir + 0.5f * nr;
    __syncthreads();
    #pragma unroll
    for (int off = 128; off; off >>= 1) {
        if (tid < off) red[tid] += red[tid + off];
        __syncthreads();
    }
    if (tid == 0) out[loss_idx] = 1e-6f * red[0] / (float)BATCH;
}

// ---------------- launch ----------------
extern "C" void kernel_launch(void* const* d_in, const int* in_sizes, int n_in,
                              void* d_out, int out_size) {
    const int*   data     = (const int*)  d_in[0];
    const int*   cell_nbr = (const int*)  d_in[1];
    const int*   drug_nbr = (const int*)  d_in[2];
    const float* table    = (const float*)d_in[3];
    const float* cell_pre = (const float*)d_in[4];
    const float* drug_pre = (const float*)d_in[5];
    const float* c1w      = (const float*)d_in[6];
    const float* c1b      = (const float*)d_in[7];
    const float* c2w      = (const float*)d_in[8];
    const float* c2b      = (const float*)d_in[9];
    const float* ow       = (const float*)d_in[10];
    const float* ob       = (const float*)d_in[11];
    const float* aw       = (const float*)d_in[12];
    const float* ab       = (const float*)d_in[13];
    const float* cw       = (const float*)d_in[14];
    float* out = (float*)d_out;

    int ia_smem = (2 * IA_ROWS + 64 + 256 + 128 + 16 + 256) * 4;
    cudaFuncSetAttribute(k_interagg, cudaFuncAttributeMaxDynamicSharedMemorySize, ia_smem);

    k_conv1<<<TSQ_N + TOT_N * 2, 256>>>(cell_pre, drug_pre, c1w, c1b, table);
    k_conv2<<<TOT_N * 2, 256>>>(c2w, c2b);

    dim3 fcg(27, KSPLIT);
    k_fc<<<fcg, 256>>>(ow);
    k_fcred<<<FCR_BLOCKS, 256>>>(ob);
    k_stats<<<1, 128>>>(0);

    k_interagg<<<TOT_N, 256, ia_smem>>>(cell_nbr, drug_nbr, table, aw, ab, cw);
    k_scoreloss<<<17, 256>>>(data, cell_nbr, drug_nbr, out, out_size - 1);
}

// round 16
// speedup vs baseline: 1.3167x; 1.0308x over previous
#include <cuda_runtime.h>

#define CELL_N 76
#define DRUG_N 764
#define TOT_N  840
#define BATCH  4096
#define NPROT  15970
#define KSPLIT 16
#define KCHUNK 512   // 8192 / KSPLIT
#define TSQ_N  ((NPROT + 7) / 8)
#define FCR_BLOCKS 53

// ---------------- scratch (device globals; no allocs allowed) ----------------
__device__ float g_pool1p[TOT_N * 4 * 66 * 68];   // padded: [plane][66][68], halo zeros
__device__ float g_pool2[TOT_N * 8 * 32 * 32];
__device__ float g_fcp  [KSPLIT * TOT_N * 64];
__device__ float g_item [TOT_N * 64];
__device__ float g_stat [4 * 64];
__device__ float4 g_sp[2 * FCR_BLOCKS * 16];
__device__ float4 g_sq[2 * FCR_BLOCKS * 16];
__device__ float g_emb  [TOT_N * 64];
__device__ float g_normsq[TOT_N];
__device__ float g_U    [CELL_N * 128];
__device__ float g_tablesq[NPROT];

// ---------------- tablesq (blocks first) + conv1 (padded output) ----------------
#define C1_STR 132
__global__ void __launch_bounds__(256, 5) k_conv1(
        const float* __restrict__ cell_pre, const float* __restrict__ drug_pre,
        const float* __restrict__ w, const float* __restrict__ b,
        const float* __restrict__ table) {
    int blk = blockIdx.x;
    int tid = threadIdx.x;
    if (blk < TSQ_N) {
        int warp = blk * 8 + (tid >> 5);
        int lane = tid & 31;
        if (warp >= NPROT) return;
        const float* r = table + warp * 64;
        float a = r[lane], bb = r[lane + 32];
        float s = a * a + bb * bb;
        #pragma unroll
        for (int o = 16; o; o >>= 1) s += __shfl_down_sync(0xffffffffu, s, o);
        if (lane == 0) g_tablesq[warp] = s;
        return;
    }
    int cblk = blk - TSQ_N;
    int half = cblk & 1;
    int gn;
    const float* x;
    if (cblk < 2 * CELL_N) { gn = cblk >> 1; x = cell_pre + gn * 16384; }
    else { int n = (cblk - 2 * CELL_N) >> 1; gn = CELL_N + n; x = drug_pre + n * 16384; }
    __shared__ float tile[66 * C1_STR];
    __shared__ float ws1[36];
    __shared__ float bs1[4];
    if (tid < 36) ws1[tid] = w[tid];
    if (tid < 4)  bs1[tid] = b[tid];
    int row0 = half * 64 - 1;
    for (int idx = tid; idx < 66 * C1_STR; idx += 256) {
        int r = idx / C1_STR, c = idx - r * C1_STR;
        int y = row0 + r, xx = c - 1;
        tile[idx] = ((unsigned)y < 128u && (unsigned)xx < 128u) ? x[y * 128 + xx] : 0.f;
    }
    // zero halo cells of the padded output (rows 0/65 full, cols 0 & 65 per half)
    for (int t = tid; t < 4 * 132; t += 256) {
        int oc = t / 132, rem = t - oc * 132;
        int base = (gn * 4 + oc) * 66 * 68;
        if (rem < 68) {
            int row = half ? 65 : 0;
            g_pool1p[base + row * 68 + rem] = 0.f;
        } else {
            int r2 = rem - 68;                       // 0..63
            int row = half * 32 + 1 + (r2 & 31);
            int col = (r2 < 32) ? 0 : 65;
            g_pool1p[base + row * 68 + col] = 0.f;
        }
    }
    __syncthreads();
    int oc = tid >> 6, t64 = tid & 63;
    float wr[9];
    #pragma unroll
    for (int t = 0; t < 9; t++) wr[t] = ws1[oc * 9 + t];
    float bv = bs1[oc];
    #pragma unroll
    for (int i = 0; i < 16; i++) {
        int pos = t64 + i * 64;
        int oy = pos >> 5, oxp = pos & 31;
        float pt[4][6];
        #pragma unroll
        for (int rr = 0; rr < 4; rr++) {
            const float* base = &tile[(2 * oy + rr) * C1_STR + 4 * oxp];
            float4 a = *(const float4*)base;
            float2 b2 = *(const float2*)(base + 4);
            pt[rr][0] = a.x; pt[rr][1] = a.y; pt[rr][2] = a.z;
            pt[rr][3] = a.w; pt[rr][4] = b2.x; pt[rr][5] = b2.y;
        }
        float q[8];
        #pragma unroll
        for (int k = 0; k < 8; k++) q[k] = bv;
        #pragma unroll
        for (int dy = 0; dy < 3; dy++)
        #pragma unroll
        for (int dx = 0; dx < 3; dx++) {
            float wv = wr[dy * 3 + dx];
            q[0] += pt[dy    ][dx    ] * wv;
            q[1] += pt[dy    ][dx + 1] * wv;
            q[2] += pt[dy + 1][dx    ] * wv;
            q[3] += pt[dy + 1][dx + 1] * wv;
            q[4] += pt[dy    ][dx + 2] * wv;
            q[5] += pt[dy    ][dx + 3] * wv;
            q[6] += pt[dy + 1][dx + 2] * wv;
            q[7] += pt[dy + 1][dx + 3] * wv;
        }
        float m0 = fmaxf(fmaxf(q[0], q[1]), fmaxf(q[2], q[3]));
        float m1 = fmaxf(fmaxf(q[4], q[5]), fmaxf(q[6], q[7]));
        int basep = ((gn * 4 + oc) * 66 + half * 32 + oy + 1) * 68 + 2 * oxp + 1;
        g_pool1p[basep    ] = fmaxf(m0, 0.f);
        g_pool1p[basep + 1] = fmaxf(m1, 0.f);
    }
}

// ---------------- conv2 (4->8): predicate-free float4 tile load ----------------
#define C2_STR 68
#define C2_CH  (34 * C2_STR)
__global__ void __launch_bounds__(256, 4) k_conv2(
        const float* __restrict__ w, const float* __restrict__ b) {
    int n = blockIdx.x >> 1, half = blockIdx.x & 1;
    __shared__ float tile[4 * C2_CH];
    __shared__ float ws[288];
    int tid = threadIdx.x;
    for (int i = tid; i < 288; i += 256) ws[i] = w[i];
    const float4* src = (const float4*)g_pool1p;
    for (int idx = tid; idx < 4 * 34 * 17; idx += 256) {
        int c = idx / (34 * 17), rem = idx - c * (34 * 17);
        int r = rem / 17, f = rem - r * 17;
        *(float4*)&tile[c * C2_CH + r * C2_STR + f * 4] =
            src[((n * 4 + c) * 66 + 32 * half + r) * 17 + f];
    }
    __syncthreads();
    int oc = tid >> 5, lane = tid & 31;
    float bs = b[oc];
    #pragma unroll
    for (int ic = 0; ic < 4; ic++) {
        float q[2][8];
        #pragma unroll
        for (int i2 = 0; i2 < 2; i2++)
            #pragma unroll
            for (int k = 0; k < 8; k++) q[i2][k] = bs;
        #pragma unroll
        for (int c = 0; c < 4; c++) {
            float wr[9];
            #pragma unroll
            for (int t = 0; t < 9; t++) wr[t] = ws[oc * 36 + c * 9 + t];
            #pragma unroll
            for (int i2 = 0; i2 < 2; i2++) {
                int pos = lane + (ic * 2 + i2) * 32;
                int oy = pos >> 4, oxp = pos & 15;
                float pt[4][6];
                #pragma unroll
                for (int rr = 0; rr < 4; rr++) {
                    const float* base = &tile[c * C2_CH + (2 * oy + rr) * C2_STR + 4 * oxp];
                    float4 a = *(const float4*)base;
                    float2 b2 = *(const float2*)(base + 4);
                    pt[rr][0] = a.x; pt[rr][1] = a.y; pt[rr][2] = a.z;
                    pt[rr][3] = a.w; pt[rr][4] = b2.x; pt[rr][5] = b2.y;
                }
                #pragma unroll
                for (int dy = 0; dy < 3; dy++)
                #pragma unroll
                for (int dx = 0; dx < 3; dx++) {
                    float wv = wr[dy * 3 + dx];
                    q[i2][0] += pt[dy    ][dx    ] * wv;
                    q[i2][1] += pt[dy    ][dx + 1] * wv;
                    q[i2][2] += pt[dy + 1][dx    ] * wv;
                    q[i2][3] += pt[dy + 1][dx + 1] * wv;
                    q[i2][4] += pt[dy    ][dx + 2] * wv;
                    q[i2][5] += pt[dy    ][dx + 3] * wv;
                    q[i2][6] += pt[dy + 1][dx + 2] * wv;
                    q[i2][7] += pt[dy + 1][dx + 3] * wv;
                }
            }
        }
        #pragma unroll
        for (int i2 = 0; i2 < 2; i2++) {
            int pos = lane + (ic * 2 + i2) * 32;
            int oy = pos >> 4, oxp = pos & 15;
            float m0 = fmaxf(fmaxf(q[i2][0], q[i2][1]), fmaxf(q[i2][2], q[i2][3]));
            float m1 = fmaxf(fmaxf(q[i2][4], q[i2][5]), fmaxf(q[i2][6], q[i2][7]));
            float2 v = make_float2(fmaxf(m0, 0.f), fmaxf(m1, 0.f));
            *(float2*)&g_pool2[((n * 8 + oc) * 32 + half * 16 + oy) * 32 + 2 * oxp] = v;
        }
    }
}

// ---------------- FC GEMM: XOR-swizzled Ws, conflict-free float4 LDS ----------------
__global__ void __launch_bounds__(256) k_fc(const float* __restrict__ W) {
    int m0 = blockIdx.x * 32;
    int kb = blockIdx.y;
    int k0 = kb * KCHUNK;
    __shared__ float Xs[32][64];
    __shared__ float Ws[64][64];           // physical f' = f ^ (j&7)
    int tid = threadIdx.x;
    int tm = tid >> 5, tn = tid & 31;
    int s7 = tn & 7;
    const float4* P4 = (const float4*)g_pool2;
    const float4* W4 = (const float4*)W;
    float acc[4][2] = {};
    for (int kt = 0; kt < KCHUNK; kt += 64) {
        int kbase4 = (k0 + kt) >> 2;
        #pragma unroll
        for (int i = 0; i < 2; i++) {
            int idx = tid + i * 256;
            int r = idx >> 4, f = idx & 15;
            int m = m0 + r;
            float4 v = (m < TOT_N) ? P4[m * 2048 + kbase4 + f]
                                   : make_float4(0.f, 0.f, 0.f, 0.f);
            *(float4*)&Xs[r][f * 4] = v;
        }
        #pragma unroll
        for (int i = 0; i < 4; i++) {
            int idx = tid + i * 256;
            int j = idx >> 4, f = idx & 15;
            *(float4*)&Ws[j][4 * (f ^ (j & 7))] = W4[j * 2048 + kbase4 + f];
        }
        __syncthreads();
        #pragma unroll
        for (int kk = 0; kk < 64; kk += 4) {
            int kkg = kk >> 2;
            float4 w0 = *(const float4*)&Ws[tn     ][4 * (kkg ^ s7)];
            float4 w1 = *(const float4*)&Ws[tn + 32][4 * (kkg ^ s7)];
            #pragma unroll
            for (int r = 0; r < 4; r++) {
                float4 xv = *(const float4*)&Xs[tm * 4 + r][kk];
                acc[r][0] += xv.x * w0.x + xv.y * w0.y + xv.z * w0.z + xv.w * w0.w;
                acc[r][1] += xv.x * w1.x + xv.y * w1.y + xv.z * w1.z + xv.w * w1.w;
            }
        }
        __syncthreads();
    }
    #pragma unroll
    for (int r = 0; r < 4; r++) {
        int m = m0 + tm * 4 + r;
        if (m < TOT_N) {
            g_fcp[(kb * TOT_N + m) * 64 + tn     ] = acc[r][0];
            g_fcp[(kb * TOT_N + m) * 64 + tn + 32] = acc[r][1];
        }
    }
}

// ---------------- fcred: K-split reduce + bias -> g_item, plus stats partials ----------------
__global__ void __launch_bounds__(256) k_fcred(const float* __restrict__ b) {
    int tid = threadIdx.x, blk = blockIdx.x;
    int v = blk * 256 + tid;
    bool ok = v < TOT_N * 16;
    int q4 = v & 15;
    float4 s = make_float4(0.f, 0.f, 0.f, 0.f);
    if (ok) {
        s = *(const float4*)&b[q4 * 4];
        #pragma unroll
        for (int kb = 0; kb < KSPLIT; kb++) {
            float4 p = *(const float4*)&g_fcp[kb * TOT_N * 64 + v * 4];
            s.x += p.x; s.y += p.y; s.z += p.z; s.w += p.w;
        }
        *(float4*)&g_item[v * 4] = s;
    }
    __shared__ float4 sm_s[256];
    __shared__ float4 sm_q[256];
    sm_s[tid] = s;
    sm_q[tid] = make_float4(s.x * s.x, s.y * s.y, s.z * s.z, s.w * s.w);
    __syncthreads();
    if (tid < 32) {
        int q = tid & 15, g = tid >> 4;
        float4 S = make_float4(0.f, 0.f, 0.f, 0.f);
        float4 Q = make_float4(0.f, 0.f, 0.f, 0.f);
        #pragma unroll
        for (int r = 0; r < 16; r++) {
            int row = blk * 16 + r;
            int grp = (row < CELL_N) ? 0 : 1;
            if (row < TOT_N && grp == g) {
                float4 a = sm_s[r * 16 + q];
                float4 c = sm_q[r * 16 + q];
                S.x += a.x; S.y += a.y; S.z += a.z; S.w += a.w;
                Q.x += c.x; Q.y += c.y; Q.z += c.z; Q.w += c.w;
            }
        }
        g_sp[(g * FCR_BLOCKS + blk) * 16 + q] = S;
        g_sq[(g * FCR_BLOCKS + blk) * 16 + q] = Q;
    }
}

// ---------------- final stats ----------------
__global__ void k_stats(int dummy) {
    int tid = threadIdx.x;
    int g = tid >> 6, j = tid & 63;
    int q = j >> 2, c = j & 3;
    const float* sp = (const float*)g_sp;
    const float* sq = (const float*)g_sq;
    float S = 0.f, Q = 0.f;
    for (int blk = 0; blk < FCR_BLOCKS; blk++) {
        int idx = ((g * FCR_BLOCKS + blk) * 16 + q) * 4 + c;
        S += sp[idx];
        Q += sq[idx];
    }
    float N = g ? (float)DRUG_N : (float)CELL_N;
    float m = S / N;
    float var = (Q - N * m * m) / (N - 1.f);
    g_stat[g * 128 + j] = m;
    g_stat[g * 128 + 64 + j] = rsqrtf(var);
}

// ---------------- interact + agg fused ----------------
#define IA_ROWS (128 * 65)
__global__ void __launch_bounds__(256) k_interagg(
        const int* __restrict__ cell_nbr, const int* __restrict__ drug_nbr,
        const float* __restrict__ table,
        const float* __restrict__ W, const float* __restrict__ b,
        const float* __restrict__ combw) {
    int n = blockIdx.x;
    const int* nbr;
    int sbase;
    if (n < CELL_N) { nbr = cell_nbr + n * 256; sbase = 0; }
    else { nbr = drug_nbr + (n - CELL_N) * 256; sbase = 128; }

    extern __shared__ float sm[];
    float* rows = sm;
    float* it   = sm + 2 * IA_ROWS;
    float* sc   = it + 64;
    float* xr   = sc + 256;
    float* wred = xr + 128;
    float* part = wred + 16;
    __shared__ int idxs[256];

    int tid = threadIdx.x;
    int warp = tid >> 5, lane = tid & 31;
    int hop = tid >> 7, wg = tid & 127;
    idxs[tid] = nbr[tid];
    if (tid < 64)
        it[tid] = (g_item[n * 64 + tid] - g_stat[sbase + tid]) * g_stat[sbase + 64 + tid];
    __syncthreads();
    const float4* t4 = (const float4*)table;
    for (int e = tid; e < 2 * 128 * 16; e += 256) {
        int hk = e >> 4, q = e & 15;
        int h = hk >> 7, k = hk & 127;
        float4 v = t4[idxs[h * 128 + k] * 16 + q];
        float* dst = &rows[h * IA_ROWS + k * 65 + q * 4];
        dst[0] = v.x; dst[1] = v.y; dst[2] = v.z; dst[3] = v.w;
    }
    __syncthreads();
    const float* myrow = &rows[hop * IA_ROWS + wg * 65];
    float s = 0.f;
    #pragma unroll 8
    for (int d = 0; d < 64; d++) s += myrow[d] * it[d];
    float m = s;
    #pragma unroll
    for (int o = 16; o; o >>= 1) m = fmaxf(m, __shfl_xor_sync(0xffffffffu, m, o));
    if (lane == 0) wred[warp] = m;
    __syncthreads();
    int wb = (hop << 2);
    float mx = fmaxf(fmaxf(wred[wb], wred[wb + 1]), fmaxf(wred[wb + 2], wred[wb + 3]));
    float e = expf(s - mx);
    sc[tid] = e;
    float t = e;
    #pragma unroll
    for (int o = 16; o; o >>= 1) t += __shfl_xor_sync(0xffffffffu, t, o);
    if (lane == 0) wred[8 + warp] = t;
    __syncthreads();
    float inv = 1.f / (wred[8 + wb] + wred[9 + wb] + wred[10 + wb] + wred[11 + wb]);
    int d = wg & 63, kh = wg >> 6;
    const float* rb = &rows[hop * IA_ROWS + (kh * 64) * 65];
    const float* sb = &sc[hop * 128 + kh * 64];
    float o = 0.f;
    #pragma unroll 8
    for (int k2 = 0; k2 < 64; k2++) o += sb[k2] * rb[k2 * 65 + d];
    part[tid] = o;
    __syncthreads();
    if (wg < 64) {
        int base = hop << 7;
        xr[hop * 64 + wg] = (part[base + wg] + part[base + 64 + wg]) * inv;
    }
    __syncthreads();
    int j = tid & 63, sl = tid >> 6;
    float ag = 0.f;
    const float* wrow = &W[j * 128 + sl * 32];
    const float* xs = &xr[sl * 32];
    #pragma unroll 8
    for (int t2 = 0; t2 < 32; t2++) ag += wrow[t2] * xs[t2];
    part[tid] = ag;
    __syncthreads();
    if (tid < 64) {
        float v = part[tid] + part[tid + 64] + part[tid + 128] + part[tid + 192] + b[tid];
        g_emb[n * 64 + tid] = v;
        it[tid] = v;
        sc[tid] = v * v;
    }
    __syncthreads();
    if (tid < 32) {
        float v = sc[tid] + sc[tid + 32];
        #pragma unroll
        for (int o2 = 16; o2; o2 >>= 1) v += __shfl_down_sync(0xffffffffu, v, o2);
        if (tid == 0) g_normsq[n] = v;
    }
    if (n < CELL_N && tid < 128) {
        float s2 = 0.f;
        #pragma unroll 8
        for (int j2 = 0; j2 < 64; j2++) s2 += combw[j2 * 128 + tid] * it[j2];
        g_U[n * 128 + tid] = s2;
    }
}

// ---------------- score (blocks 0..15, float4) + loss (block 16) ----------------
__global__ void __launch_bounds__(256) k_scoreloss(
        const int* __restrict__ data, const int* __restrict__ cell_nbr,
        const int* __restrict__ drug_nbr, float* __restrict__ out, int loss_idx) {
    int blk = blockIdx.x;
    int tid = threadIdx.x;
    if (blk < 16) {
        int bidx = blk * 256 + tid;
        int c  = data[3 * bidx];
        int d1 = data[3 * bidx + 1];
        int d2 = data[3 * bidx + 2];
        const float4* e1 = (const float4*)(g_emb + (CELL_N + d1) * 64);
        const float4* e2 = (const float4*)(g_emb + (CELL_N + d2) * 64);
        const float4* u  = (const float4*)(g_U + c * 128);
        float s = 0.f;
        #pragma unroll
        for (int t = 0; t < 16; t++) {
            float4 a = e1[t], bb = e2[t], u0 = u[t], u1 = u[16 + t];
            s += a.x * u0.x + a.y * u0.y + a.z * u0.z + a.w * u0.w;
            s += bb.x * u1.x + bb.y * u1.y + bb.z * u1.z + bb.w * u1.w;
            s -= a.x * bb.x + a.y * bb.y + a.z * bb.z + a.w * bb.w;
        }
        out[bidx] = s;
        return;
    }
    __shared__ float nsq[TOT_N];
    __shared__ float red[256];
    for (int i = tid; i < TOT_N; i += 256) nsq[i] = g_normsq[i];
    __syncthreads();
    float ir = 0.f;
    for (int bidx = tid; bidx < BATCH; bidx += 256) {
        int c  = data[3 * bidx];
        int d1 = data[3 * bidx + 1];
        int d2 = data[3 * bidx + 2];
        ir += nsq[c] + nsq[CELL_N + d1] + nsq[CELL_N + d2];
    }
    float nr = 0.f;
    for (int e = tid; e < 1536; e += 256) {
        int set = e >> 8, off = e & 255;
        int hop = set / 3, which = set - hop * 3;
        int nodeidx = data[hop * 3 + which];
        int p = (which == 0) ? cell_nbr[nodeidx * 256 + off] : drug_nbr[nodeidx * 256 + off];
        nr += g_tablesq[p];
    }
    red[tid] = 0.5f * ir + 0.5f * nr;
    __syncthreads();
    #pragma unroll
    for (int off = 128; off; off >>= 1) {
        if (tid < off) red[tid] += red[tid + off];
        __syncthreads();
    }
    if (tid == 0) out[loss_idx] = 1e-6f * red[0] / (float)BATCH;
}

// ---------------- launch ----------------
extern "C" void kernel_launch(void* const* d_in, const int* in_sizes, int n_in,
                              void* d_out, int out_size) {
    const int*   data     = (const int*)  d_in[0];
    const int*   cell_nbr = (const int*)  d_in[1];
    const int*   drug_nbr = (const int*)  d_in[2];
    const float* table    = (const float*)d_in[3];
    const float* cell_pre = (const float*)d_in[4];
    const float* drug_pre = (const float*)d_in[5];
    const float* c1w      = (const float*)d_in[6];
    const float* c1b      = (const float*)d_in[7];
    const float* c2w      = (const float*)d_in[8];
    const float* c2b      = (const float*)d_in[9];
    const float* ow       = (const float*)d_in[10];
    const float* ob       = (const float*)d_in[11];
    const float* aw       = (const float*)d_in[12];
    const float* ab       = (const float*)d_in[13];
    const float* cw       = (const float*)d_in[14];
    float* out = (float*)d_out;

    int ia_smem = (2 * IA_ROWS + 64 + 256 + 128 + 16 + 256) * 4;
    cudaFuncSetAttribute(k_interagg, cudaFuncAttributeMaxDynamicSharedMemorySize, ia_smem);

    k_conv1<<<TSQ_N + TOT_N * 2, 256>>>(cell_pre, drug_pre, c1w, c1b, table);
    k_conv2<<<TOT_N * 2, 256>>>(c2w, c2b);

    dim3 fcg(27, KSPLIT);
    k_fc<<<fcg, 256>>>(ow);
    k_fcred<<<FCR_BLOCKS, 256>>>(ob);
    k_stats<<<1, 128>>>(0);

    k_interagg<<<TOT_N, 256, ia_smem>>>(cell_nbr, drug_nbr, table, aw, ab, cw);
    k_scoreloss<<<17, 256>>>(data, cell_nbr, drug_nbr, out, out_size - 1);
}

// round 17
// speedup vs baseline: 1.3390x; 1.0169x over previous
#include <cuda_runtime.h>

#define CELL_N 76
#define DRUG_N 764
#define TOT_N  840
#define BATCH  4096
#define NPROT  15970
#define KSPLIT 16
#define KCHUNK 512   // 8192 / KSPLIT
#define TSQ_N  ((NPROT + 7) / 8)
#define FCR_BLOCKS 53

// ---------------- scratch (device globals; no allocs allowed) ----------------
__device__ float g_pool1p[TOT_N * 4 * 66 * 68];   // padded: [plane][66][68], halo zeros
__device__ float g_pool2[TOT_N * 8 * 32 * 32];
__device__ float g_fcp  [KSPLIT * TOT_N * 64];
__device__ float g_item [TOT_N * 64];
__device__ float g_stat [4 * 64];
__device__ float4 g_sp[2 * FCR_BLOCKS * 16];
__device__ float4 g_sq[2 * FCR_BLOCKS * 16];
__device__ float g_emb  [TOT_N * 64];
__device__ float g_normsq[TOT_N];
__device__ float g_U    [CELL_N * 128];
__device__ float g_tablesq[NPROT];
__device__ unsigned g_ctr;                 // fcred completion counter

// ---------------- tablesq (blocks first) + conv1 (padded output) ----------------
#define C1_STR 132
__global__ void __launch_bounds__(256, 5) k_conv1(
        const float* __restrict__ cell_pre, const float* __restrict__ drug_pre,
        const float* __restrict__ w, const float* __restrict__ b,
        const float* __restrict__ table) {
    int blk = blockIdx.x;
    int tid = threadIdx.x;
    if (blk < TSQ_N) {
        int warp = blk * 8 + (tid >> 5);
        int lane = tid & 31;
        if (warp >= NPROT) return;
        const float* r = table + warp * 64;
        float a = r[lane], bb = r[lane + 32];
        float s = a * a + bb * bb;
        #pragma unroll
        for (int o = 16; o; o >>= 1) s += __shfl_down_sync(0xffffffffu, s, o);
        if (lane == 0) g_tablesq[warp] = s;
        return;
    }
    int cblk = blk - TSQ_N;
    int half = cblk & 1;
    int gn;
    const float* x;
    if (cblk < 2 * CELL_N) { gn = cblk >> 1; x = cell_pre + gn * 16384; }
    else { int n = (cblk - 2 * CELL_N) >> 1; gn = CELL_N + n; x = drug_pre + n * 16384; }
    __shared__ float tile[66 * C1_STR];
    __shared__ float ws1[36];
    __shared__ float bs1[4];
    if (tid < 36) ws1[tid] = w[tid];
    if (tid < 4)  bs1[tid] = b[tid];
    int row0 = half * 64 - 1;
    // interior: float4 loads (rows 16B-aligned), scalar scatter to tile (+1 col shift)
    const float4* x4 = (const float4*)x;
    for (int idx = tid; idx < 66 * 32; idx += 256) {
        int r = idx >> 5, k = idx & 31;
        int y = row0 + r;
        float4 v = ((unsigned)y < 128u) ? x4[y * 32 + k] : make_float4(0.f, 0.f, 0.f, 0.f);
        float* d = &tile[r * C1_STR + 4 * k + 1];
        d[0] = v.x; d[1] = v.y; d[2] = v.z; d[3] = v.w;
    }
    // halo columns: c = 0, 129, 130, 131
    for (int idx = tid; idx < 66 * 4; idx += 256) {
        int r = idx >> 2, e = idx & 3;
        int c = (e == 0) ? 0 : (128 + e);
        tile[r * C1_STR + c] = 0.f;
    }
    // zero halo cells of the padded output
    for (int t = tid; t < 4 * 132; t += 256) {
        int oc = t / 132, rem = t - oc * 132;
        int base = (gn * 4 + oc) * 66 * 68;
        if (rem < 68) {
            int row = half ? 65 : 0;
            g_pool1p[base + row * 68 + rem] = 0.f;
        } else {
            int r2 = rem - 68;
            int row = half * 32 + 1 + (r2 & 31);
            int col = (r2 < 32) ? 0 : 65;
            g_pool1p[base + row * 68 + col] = 0.f;
        }
    }
    __syncthreads();
    int oc = tid >> 6, t64 = tid & 63;
    float wr[9];
    #pragma unroll
    for (int t = 0; t < 9; t++) wr[t] = ws1[oc * 9 + t];
    float bv = bs1[oc];
    #pragma unroll
    for (int i = 0; i < 16; i++) {
        int pos = t64 + i * 64;
        int oy = pos >> 5, oxp = pos & 31;
        float pt[4][6];
        #pragma unroll
        for (int rr = 0; rr < 4; rr++) {
            const float* base = &tile[(2 * oy + rr) * C1_STR + 4 * oxp];
            float4 a = *(const float4*)base;
            float2 b2 = *(const float2*)(base + 4);
            pt[rr][0] = a.x; pt[rr][1] = a.y; pt[rr][2] = a.z;
            pt[rr][3] = a.w; pt[rr][4] = b2.x; pt[rr][5] = b2.y;
        }
        float q[8];
        #pragma unroll
        for (int k = 0; k < 8; k++) q[k] = bv;
        #pragma unroll
        for (int dy = 0; dy < 3; dy++)
        #pragma unroll
        for (int dx = 0; dx < 3; dx++) {
            float wv = wr[dy * 3 + dx];
            q[0] += pt[dy    ][dx    ] * wv;
            q[1] += pt[dy    ][dx + 1] * wv;
            q[2] += pt[dy + 1][dx    ] * wv;
            q[3] += pt[dy + 1][dx + 1] * wv;
            q[4] += pt[dy    ][dx + 2] * wv;
            q[5] += pt[dy    ][dx + 3] * wv;
            q[6] += pt[dy + 1][dx + 2] * wv;
            q[7] += pt[dy + 1][dx + 3] * wv;
        }
        float m0 = fmaxf(fmaxf(q[0], q[1]), fmaxf(q[2], q[3]));
        float m1 = fmaxf(fmaxf(q[4], q[5]), fmaxf(q[6], q[7]));
        int basep = ((gn * 4 + oc) * 66 + half * 32 + oy + 1) * 68 + 2 * oxp + 1;
        g_pool1p[basep    ] = fmaxf(m0, 0.f);
        g_pool1p[basep + 1] = fmaxf(m1, 0.f);
    }
}

// ---------------- conv2 (4->8): predicate-free float4 tile load ----------------
#define C2_STR 68
#define C2_CH  (34 * C2_STR)
__global__ void __launch_bounds__(256, 4) k_conv2(
        const float* __restrict__ w, const float* __restrict__ b) {
    int n = blockIdx.x >> 1, half = blockIdx.x & 1;
    __shared__ float tile[4 * C2_CH];
    __shared__ float ws[288];
    int tid = threadIdx.x;
    for (int i = tid; i < 288; i += 256) ws[i] = w[i];
    const float4* src = (const float4*)g_pool1p;
    for (int idx = tid; idx < 4 * 34 * 17; idx += 256) {
        int c = idx / (34 * 17), rem = idx - c * (34 * 17);
        int r = rem / 17, f = rem - r * 17;
        *(float4*)&tile[c * C2_CH + r * C2_STR + f * 4] =
            src[((n * 4 + c) * 66 + 32 * half + r) * 17 + f];
    }
    __syncthreads();
    int oc = tid >> 5, lane = tid & 31;
    float bs = b[oc];
    #pragma unroll
    for (int ic = 0; ic < 4; ic++) {
        float q[2][8];
        #pragma unroll
        for (int i2 = 0; i2 < 2; i2++)
            #pragma unroll
            for (int k = 0; k < 8; k++) q[i2][k] = bs;
        #pragma unroll
        for (int c = 0; c < 4; c++) {
            float wr[9];
            #pragma unroll
            for (int t = 0; t < 9; t++) wr[t] = ws[oc * 36 + c * 9 + t];
            #pragma unroll
            for (int i2 = 0; i2 < 2; i2++) {
                int pos = lane + (ic * 2 + i2) * 32;
                int oy = pos >> 4, oxp = pos & 15;
                float pt[4][6];
                #pragma unroll
                for (int rr = 0; rr < 4; rr++) {
                    const float* base = &tile[c * C2_CH + (2 * oy + rr) * C2_STR + 4 * oxp];
                    float4 a = *(const float4*)base;
                    float2 b2 = *(const float2*)(base + 4);
                    pt[rr][0] = a.x; pt[rr][1] = a.y; pt[rr][2] = a.z;
                    pt[rr][3] = a.w; pt[rr][4] = b2.x; pt[rr][5] = b2.y;
                }
                #pragma unroll
                for (int dy = 0; dy < 3; dy++)
                #pragma unroll
                for (int dx = 0; dx < 3; dx++) {
                    float wv = wr[dy * 3 + dx];
                    q[i2][0] += pt[dy    ][dx    ] * wv;
                    q[i2][1] += pt[dy    ][dx + 1] * wv;
                    q[i2][2] += pt[dy + 1][dx    ] * wv;
                    q[i2][3] += pt[dy + 1][dx + 1] * wv;
                    q[i2][4] += pt[dy    ][dx + 2] * wv;
                    q[i2][5] += pt[dy    ][dx + 3] * wv;
                    q[i2][6] += pt[dy + 1][dx + 2] * wv;
                    q[i2][7] += pt[dy + 1][dx + 3] * wv;
                }
            }
        }
        #pragma unroll
        for (int i2 = 0; i2 < 2; i2++) {
            int pos = lane + (ic * 2 + i2) * 32;
            int oy = pos >> 4, oxp = pos & 15;
            float m0 = fmaxf(fmaxf(q[i2][0], q[i2][1]), fmaxf(q[i2][2], q[i2][3]));
            float m1 = fmaxf(fmaxf(q[i2][4], q[i2][5]), fmaxf(q[i2][6], q[i2][7]));
            float2 v = make_float2(fmaxf(m0, 0.f), fmaxf(m1, 0.f));
            *(float2*)&g_pool2[((n * 8 + oc) * 32 + half * 16 + oy) * 32 + 2 * oxp] = v;
        }
    }
}

// ---------------- FC GEMM: XOR-swizzled Ws, conflict-free float4 LDS ----------------
__global__ void __launch_bounds__(256) k_fc(const float* __restrict__ W) {
    if (blockIdx.x == 0 && blockIdx.y == 0 && threadIdx.x == 0) g_ctr = 0u;
    int m0 = blockIdx.x * 32;
    int kb = blockIdx.y;
    int k0 = kb * KCHUNK;
    __shared__ float Xs[32][64];
    __shared__ float Ws[64][64];           // physical f' = f ^ (j&7)
    int tid = threadIdx.x;
    int tm = tid >> 5, tn = tid & 31;
    int s7 = tn & 7;
    const float4* P4 = (const float4*)g_pool2;
    const float4* W4 = (const float4*)W;
    float acc[4][2] = {};
    for (int kt = 0; kt < KCHUNK; kt += 64) {
        int kbase4 = (k0 + kt) >> 2;
        #pragma unroll
        for (int i = 0; i < 2; i++) {
            int idx = tid + i * 256;
            int r = idx >> 4, f = idx & 15;
            int m = m0 + r;
            float4 v = (m < TOT_N) ? P4[m * 2048 + kbase4 + f]
                                   : make_float4(0.f, 0.f, 0.f, 0.f);
            *(float4*)&Xs[r][f * 4] = v;
        }
        #pragma unroll
        for (int i = 0; i < 4; i++) {
            int idx = tid + i * 256;
            int j = idx >> 4, f = idx & 15;
            *(float4*)&Ws[j][4 * (f ^ (j & 7))] = W4[j * 2048 + kbase4 + f];
        }
        __syncthreads();
        #pragma unroll
        for (int kk = 0; kk < 64; kk += 4) {
            int kkg = kk >> 2;
            float4 w0 = *(const float4*)&Ws[tn     ][4 * (kkg ^ s7)];
            float4 w1 = *(const float4*)&Ws[tn + 32][4 * (kkg ^ s7)];
            #pragma unroll
            for (int r = 0; r < 4; r++) {
                float4 xv = *(const float4*)&Xs[tm * 4 + r][kk];
                acc[r][0] += xv.x * w0.x + xv.y * w0.y + xv.z * w0.z + xv.w * w0.w;
                acc[r][1] += xv.x * w1.x + xv.y * w1.y + xv.z * w1.z + xv.w * w1.w;
            }
        }
        __syncthreads();
    }
    #pragma unroll
    for (int r = 0; r < 4; r++) {
        int m = m0 + tm * 4 + r;
        if (m < TOT_N) {
            g_fcp[(kb * TOT_N + m) * 64 + tn     ] = acc[r][0];
            g_fcp[(kb * TOT_N + m) * 64 + tn + 32] = acc[r][1];
        }
    }
}

// ---------------- fcred: K-split reduce + bias -> g_item, stats partials,
//                  last block computes final stats (no separate launch) ----------------
__global__ void __launch_bounds__(256) k_fcred(const float* __restrict__ b) {
    int tid = threadIdx.x, blk = blockIdx.x;
    int v = blk * 256 + tid;
    bool ok = v < TOT_N * 16;
    int q4 = v & 15;
    float4 s = make_float4(0.f, 0.f, 0.f, 0.f);
    if (ok) {
        s = *(const float4*)&b[q4 * 4];
        #pragma unroll
        for (int kb = 0; kb < KSPLIT; kb++) {
            float4 p = *(const float4*)&g_fcp[kb * TOT_N * 64 + v * 4];
            s.x += p.x; s.y += p.y; s.z += p.z; s.w += p.w;
        }
        *(float4*)&g_item[v * 4] = s;
    }
    __shared__ float4 sm_s[256];
    __shared__ float4 sm_q[256];
    sm_s[tid] = s;
    sm_q[tid] = make_float4(s.x * s.x, s.y * s.y, s.z * s.z, s.w * s.w);
    __syncthreads();
    if (tid < 32) {
        int q = tid & 15, g = tid >> 4;
        float4 S = make_float4(0.f, 0.f, 0.f, 0.f);
        float4 Q = make_float4(0.f, 0.f, 0.f, 0.f);
        #pragma unroll
        for (int r = 0; r < 16; r++) {
            int row = blk * 16 + r;
            int grp = (row < CELL_N) ? 0 : 1;
            if (row < TOT_N && grp == g) {
                float4 a = sm_s[r * 16 + q];
                float4 c = sm_q[r * 16 + q];
                S.x += a.x; S.y += a.y; S.z += a.z; S.w += a.w;
                Q.x += c.x; Q.y += c.y; Q.z += c.z; Q.w += c.w;
            }
        }
        g_sp[(g * FCR_BLOCKS + blk) * 16 + q] = S;
        g_sq[(g * FCR_BLOCKS + blk) * 16 + q] = Q;
    }
    // last-block-done: final stats reduction
    __threadfence();
    __shared__ int last;
    __syncthreads();
    if (tid == 0) last = (atomicAdd(&g_ctr, 1u) == FCR_BLOCKS - 1) ? 1 : 0;
    __syncthreads();
    if (last && tid < 128) {
        int g = tid >> 6, j = tid & 63;
        int q = j >> 2, c = j & 3;
        const float* sp = (const float*)g_sp;
        const float* sq = (const float*)g_sq;
        float S = 0.f, Q = 0.f;
        for (int bk = 0; bk < FCR_BLOCKS; bk++) {
            int idx = ((g * FCR_BLOCKS + bk) * 16 + q) * 4 + c;
            S += sp[idx];
            Q += sq[idx];
        }
        float N = g ? (float)DRUG_N : (float)CELL_N;
        float m = S / N;
        float var = (Q - N * m * m) / (N - 1.f);
        g_stat[g * 128 + j] = m;
        g_stat[g * 128 + 64 + j] = rsqrtf(var);
    }
}

// ---------------- interact + agg fused ----------------
#define IA_ROWS (128 * 65)
__global__ void __launch_bounds__(256) k_interagg(
        const int* __restrict__ cell_nbr, const int* __restrict__ drug_nbr,
        const float* __restrict__ table,
        const float* __restrict__ W, const float* __restrict__ b,
        const float* __restrict__ combw) {
    int n = blockIdx.x;
    const int* nbr;
    int sbase;
    if (n < CELL_N) { nbr = cell_nbr + n * 256; sbase = 0; }
    else { nbr = drug_nbr + (n - CELL_N) * 256; sbase = 128; }

    extern __shared__ float sm[];
    float* rows = sm;
    float* it   = sm + 2 * IA_ROWS;
    float* sc   = it + 64;
    float* xr   = sc + 256;
    float* wred = xr + 128;
    float* part = wred + 16;
    __shared__ int idxs[256];

    int tid = threadIdx.x;
    int warp = tid >> 5, lane = tid & 31;
    int hop = tid >> 7, wg = tid & 127;
    idxs[tid] = nbr[tid];
    if (tid < 64)
        it[tid] = (g_item[n * 64 + tid] - g_stat[sbase + tid]) * g_stat[sbase + 64 + tid];
    __syncthreads();
    const float4* t4 = (const float4*)table;
    for (int e = tid; e < 2 * 128 * 16; e += 256) {
        int hk = e >> 4, q = e & 15;
        int h = hk >> 7, k = hk & 127;
        float4 v = t4[idxs[h * 128 + k] * 16 + q];
        float* dst = &rows[h * IA_ROWS + k * 65 + q * 4];
        dst[0] = v.x; dst[1] = v.y; dst[2] = v.z; dst[3] = v.w;
    }
    __syncthreads();
    const float* myrow = &rows[hop * IA_ROWS + wg * 65];
    float s = 0.f;
    #pragma unroll 8
    for (int d = 0; d < 64; d++) s += myrow[d] * it[d];
    float m = s;
    #pragma unroll
    for (int o = 16; o; o >>= 1) m = fmaxf(m, __shfl_xor_sync(0xffffffffu, m, o));
    if (lane == 0) wred[warp] = m;
    __syncthreads();
    int wb = (hop << 2);
    float mx = fmaxf(fmaxf(wred[wb], wred[wb + 1]), fmaxf(wred[wb + 2], wred[wb + 3]));
    float e = expf(s - mx);
    sc[tid] = e;
    float t = e;
    #pragma unroll
    for (int o = 16; o; o >>= 1) t += __shfl_xor_sync(0xffffffffu, t, o);
    if (lane == 0) wred[8 + warp] = t;
    __syncthreads();
    float inv = 1.f / (wred[8 + wb] + wred[9 + wb] + wred[10 + wb] + wred[11 + wb]);
    int d = wg & 63, kh = wg >> 6;
    const float* rb = &rows[hop * IA_ROWS + (kh * 64) * 65];
    const float* sb = &sc[hop * 128 + kh * 64];
    float o = 0.f;
    #pragma unroll 8
    for (int k2 = 0; k2 < 64; k2++) o += sb[k2] * rb[k2 * 65 + d];
    part[tid] = o;
    __syncthreads();
    if (wg < 64) {
        int base = hop << 7;
        xr[hop * 64 + wg] = (part[base + wg] + part[base + 64 + wg]) * inv;
    }
    __syncthreads();
    int j = tid & 63, sl = tid >> 6;
    float ag = 0.f;
    const float* wrow = &W[j * 128 + sl * 32];
    const float* xs = &xr[sl * 32];
    #pragma unroll 8
    for (int t2 = 0; t2 < 32; t2++) ag += wrow[t2] * xs[t2];
    part[tid] = ag;
    __syncthreads();
    if (tid < 64) {
        float v = part[tid] + part[tid + 64] + part[tid + 128] + part[tid + 192] + b[tid];
        g_emb[n * 64 + tid] = v;
        it[tid] = v;
        sc[tid] = v * v;
    }
    __syncthreads();
    if (tid < 32) {
        float v = sc[tid] + sc[tid + 32];
        #pragma unroll
        for (int o2 = 16; o2; o2 >>= 1) v += __shfl_down_sync(0xffffffffu, v, o2);
        if (tid == 0) g_normsq[n] = v;
    }
    if (n < CELL_N && tid < 128) {
        float s2 = 0.f;
        #pragma unroll 8
        for (int j2 = 0; j2 < 64; j2++) s2 += combw[j2 * 128 + tid] * it[j2];
        g_U[n * 128 + tid] = s2;
    }
}

// ---------------- score (blocks 0..15, float4) + loss (block 16) ----------------
__global__ void __launch_bounds__(256) k_scoreloss(
        const int* __restrict__ data, const int* __restrict__ cell_nbr,
        const int* __restrict__ drug_nbr, float* __restrict__ out, int loss_idx) {
    int blk = blockIdx.x;
    int tid = threadIdx.x;
    if (blk < 16) {
        int bidx = blk * 256 + tid;
        int c  = data[3 * bidx];
        int d1 = data[3 * bidx + 1];
        int d2 = data[3 * bidx + 2];
        const float4* e1 = (const float4*)(g_emb + (CELL_N + d1) * 64);
        const float4* e2 = (const float4*)(g_emb + (CELL_N + d2) * 64);
        const float4* u  = (const float4*)(g_U + c * 128);
        float s = 0.f;
        #pragma unroll
        for (int t = 0; t < 16; t++) {
            float4 a = e1[t], bb = e2[t], u0 = u[t], u1 = u[16 + t];
            s += a.x * u0.x + a.y * u0.y + a.z * u0.z + a.w * u0.w;
            s += bb.x * u1.x + bb.y * u1.y + bb.z * u1.z + bb.w * u1.w;
            s -= a.x * bb.x + a.y * bb.y + a.z * bb.z + a.w * bb.w;
        }
        out[bidx] = s;
        return;
    }
    __shared__ float nsq[TOT_N];
    __shared__ float red[256];
    for (int i = tid; i < TOT_N; i += 256) nsq[i] = g_normsq[i];
    __syncthreads();
    float ir = 0.f;
    for (int bidx = tid; bidx < BATCH; bidx += 256) {
        int c  = data[3 * bidx];
        int d1 = data[3 * bidx + 1];
        int d2 = data[3 * bidx + 2];
        ir += nsq[c] + nsq[CELL_N + d1] + nsq[CELL_N + d2];
    }
    float nr = 0.f;
    for (int e = tid; e < 1536; e += 256) {
        int set = e >> 8, off = e & 255;
        int hop = set / 3, which = set - hop * 3;
        int nodeidx = data[hop * 3 + which];
        int p = (which == 0) ? cell_nbr[nodeidx * 256 + off] : drug_nbr[nodeidx * 256 + off];
        nr += g_tablesq[p];
    }
    red[tid] = 0.5f * ir + 0.5f * nr;
    __syncthreads();
    #pragma unroll
    for (int off = 128; off; off >>= 1) {
        if (tid < off) red[tid] += red[tid + off];
        __syncthreads();
    }
    if (tid == 0) out[loss_idx] = 1e-6f * red[0] / (float)BATCH;
}

// ---------------- launch ----------------
extern "C" void kernel_launch(void* const* d_in, const int* in_sizes, int n_in,
                              void* d_out, int out_size) {
    const int*   data     = (const int*)  d_in[0];
    const int*   cell_nbr = (const int*)  d_in[1];
    const int*   drug_nbr = (const int*)  d_in[2];
    const float* table    = (const float*)d_in[3];
    const float* cell_pre = (const float*)d_in[4];
    const float* drug_pre = (const float*)d_in[5];
    const float* c1w      = (const float*)d_in[6];
    const float* c1b      = (const float*)d_in[7];
    const float* c2w      = (const float*)d_in[8];
    const float* c2b      = (const float*)d_in[9];
    const float* ow       = (const float*)d_in[10];
    const float* ob       = (const float*)d_in[11];
    const float* aw       = (const float*)d_in[12];
    const float* ab       = (const float*)d_in[13];
    const float* cw       = (const float*)d_in[14];
    float* out = (float*)d_out;

    int ia_smem = (2 * IA_ROWS + 64 + 256 + 128 + 16 + 256) * 4;
    cudaFuncSetAttribute(k_interagg, cudaFuncAttributeMaxDynamicSharedMemorySize, ia_smem);

    k_conv1<<<TSQ_N + TOT_N * 2, 256>>>(cell_pre, drug_pre, c1w, c1b, table);
    k_conv2<<<TOT_N * 2, 256>>>(c2w, c2b);

    dim3 fcg(27, KSPLIT);
    k_fc<<<fcg, 256>>>(ow);
    k_fcred<<<FCR_BLOCKS, 256>>>(ob);

    k_interagg<<<TOT_N, 256, ia_smem>>>(cell_nbr, drug_nbr, table, aw, ab, cw);
    k_scoreloss<<<17, 256>>>(data, cell_nbr, drug_nbr, out, out_size - 1);
}